// round 12
// baseline (speedup 1.0000x reference)
#include <cuda_runtime.h>
#include <math.h>

#define NN 50000
#define EE 800000
#define RR 8
#define BB 4
#define NHH 2
#define NR (NN*RR)   // 400000
#define NEG 0.2f
#define FULLM 0xFFFFFFFFu

// ---------------- device scratch ----------------
__device__ int g_deg[NR];
__device__ int g_rowptr[NR+1];
__device__ int g_cur[NR];
__device__ int g_epack[EE];      // src | (rel << 16)
__device__ int g_bsum[512];
__device__ int g_boff[512];
__device__ int g_ctr;

__device__ float g_Z[(size_t)NN*BB*64];   // RGCN basis-folded aggregates [N, 256]
__device__ float g_h[(size_t)NN*NHH*64];  // GAT projected features
__device__ float g_sn[NN*NHH];            // att_src dot (float2-viewable)
__device__ float g_dn[NN*NHH];            // att_dst dot
__device__ float g_bufA[(size_t)NN*64];
__device__ float g_bufB[(size_t)NN*64];
__device__ float g_bufC[(size_t)NN*64];
__device__ float g_bufD[(size_t)NN*64];

// ---------------- CSR build ----------------
__global__ void k_hist(const int* __restrict__ ei, const int* __restrict__ et) {
    int e = blockIdx.x*blockDim.x + threadIdx.x;
    if (e >= EE) return;
    int dst = ei[EE + e];
    int r   = et[e];
    atomicAdd(&g_deg[dst*RR + r], 1);
}
// block scan; LAST finishing block also scans per-block sums AND self-resets g_ctr
__global__ void k_scan_block() { // 1024 threads/block
    __shared__ int sh[1024];
    __shared__ bool isLast;
    int i = blockIdx.x*1024 + threadIdx.x;
    int v = (i < NR) ? g_deg[i] : 0;
    sh[threadIdx.x] = v;
    __syncthreads();
    for (int off = 1; off < 1024; off <<= 1) {
        int t = (threadIdx.x >= off) ? sh[threadIdx.x - off] : 0;
        __syncthreads();
        sh[threadIdx.x] += t;
        __syncthreads();
    }
    if (i < NR) g_rowptr[i+1] = sh[threadIdx.x];
    if (threadIdx.x == 1023) g_bsum[blockIdx.x] = sh[1023];
    __threadfence();
    if (threadIdx.x == 0) isLast = (atomicAdd(&g_ctr, 1) == (int)gridDim.x - 1);
    __syncthreads();
    if (!isLast) return;
    int nb = gridDim.x;
    int v2 = (threadIdx.x < 512 && (int)threadIdx.x < nb) ? g_bsum[threadIdx.x] : 0;
    __syncthreads();
    if (threadIdx.x < 512) sh[threadIdx.x] = v2;
    __syncthreads();
    for (int off = 1; off < 512; off <<= 1) {
        int t = (threadIdx.x < 512 && threadIdx.x >= (unsigned)off) ? sh[threadIdx.x - off] : 0;
        __syncthreads();
        if (threadIdx.x < 512) sh[threadIdx.x] += t;
        __syncthreads();
    }
    if ((int)threadIdx.x < nb) g_boff[threadIdx.x] = sh[threadIdx.x] - v2; // exclusive
    if (threadIdx.x == 0) g_ctr = 0;   // self-reset for next graph replay
}

__device__ __forceinline__ float leaky(float v) { return v > 0.f ? v : NEG*v; }

// ---------------- RGCN per-node body (R9-proven: float2, MLP-batched) ----------
__device__ __forceinline__ void rgcn_node(int n, int lane, const float* __restrict__ X,
                                          const float* __restrict__ rc) {
    int rp = 0;
    if (lane <= 8) rp = g_rowptr[n*RR + lane];
    int s   = __shfl_sync(FULLM, rp, 0);
    int e8  = __shfl_sync(FULLM, rp, 8);
    int deg = e8 - s;
    int nxt = __shfl_down_sync(FULLM, rp, 1);
    int cseg = nxt - rp;
    float invr = (lane < 8 && cseg > 0) ? 1.0f/(float)cseg : 0.f;
    float rcw = rc[lane] * __shfl_sync(FULLM, invr, lane >> 2);
    float2 z0 = {0.f,0.f}, z1 = {0.f,0.f}, z2 = {0.f,0.f}, z3 = {0.f,0.f};
    const float2* Xb = (const float2*)X;
    for (int base = 0; base < deg; base += 32) {
        int cnt = min(32, deg - base);
        int pk = (lane < cnt) ? g_epack[s + base + lane] : 0;
        int j = 0;
        for (; j + 4 <= cnt; j += 4) {
            int p0 = __shfl_sync(FULLM, pk, j);
            int p1 = __shfl_sync(FULLM, pk, j+1);
            int p2 = __shfl_sync(FULLM, pk, j+2);
            int p3 = __shfl_sync(FULLM, pk, j+3);
            float2 v0 = Xb[(size_t)(p0 & 0xFFFF)*32 + lane];
            float2 v1 = Xb[(size_t)(p1 & 0xFFFF)*32 + lane];
            float2 v2 = Xb[(size_t)(p2 & 0xFFFF)*32 + lane];
            float2 v3 = Xb[(size_t)(p3 & 0xFFFF)*32 + lane];
            int r0 = (p0 >> 16) << 2, r1 = (p1 >> 16) << 2;
            int r2 = (p2 >> 16) << 2, r3 = (p3 >> 16) << 2;
            float w;
            w = __shfl_sync(FULLM, rcw, r0+0); z0.x += w*v0.x; z0.y += w*v0.y;
            w = __shfl_sync(FULLM, rcw, r0+1); z1.x += w*v0.x; z1.y += w*v0.y;
            w = __shfl_sync(FULLM, rcw, r0+2); z2.x += w*v0.x; z2.y += w*v0.y;
            w = __shfl_sync(FULLM, rcw, r0+3); z3.x += w*v0.x; z3.y += w*v0.y;
            w = __shfl_sync(FULLM, rcw, r1+0); z0.x += w*v1.x; z0.y += w*v1.y;
            w = __shfl_sync(FULLM, rcw, r1+1); z1.x += w*v1.x; z1.y += w*v1.y;
            w = __shfl_sync(FULLM, rcw, r1+2); z2.x += w*v1.x; z2.y += w*v1.y;
            w = __shfl_sync(FULLM, rcw, r1+3); z3.x += w*v1.x; z3.y += w*v1.y;
            w = __shfl_sync(FULLM, rcw, r2+0); z0.x += w*v2.x; z0.y += w*v2.y;
            w = __shfl_sync(FULLM, rcw, r2+1); z1.x += w*v2.x; z1.y += w*v2.y;
            w = __shfl_sync(FULLM, rcw, r2+2); z2.x += w*v2.x; z2.y += w*v2.y;
            w = __shfl_sync(FULLM, rcw, r2+3); z3.x += w*v2.x; z3.y += w*v2.y;
            w = __shfl_sync(FULLM, rcw, r3+0); z0.x += w*v3.x; z0.y += w*v3.y;
            w = __shfl_sync(FULLM, rcw, r3+1); z1.x += w*v3.x; z1.y += w*v3.y;
            w = __shfl_sync(FULLM, rcw, r3+2); z2.x += w*v3.x; z2.y += w*v3.y;
            w = __shfl_sync(FULLM, rcw, r3+3); z3.x += w*v3.x; z3.y += w*v3.y;
        }
        for (; j < cnt; j++) {
            int p0 = __shfl_sync(FULLM, pk, j);
            float2 v0 = Xb[(size_t)(p0 & 0xFFFF)*32 + lane];
            int r0 = (p0 >> 16) << 2;
            float w;
            w = __shfl_sync(FULLM, rcw, r0+0); z0.x += w*v0.x; z0.y += w*v0.y;
            w = __shfl_sync(FULLM, rcw, r0+1); z1.x += w*v0.x; z1.y += w*v0.y;
            w = __shfl_sync(FULLM, rcw, r0+2); z2.x += w*v0.x; z2.y += w*v0.y;
            w = __shfl_sync(FULLM, rcw, r0+3); z3.x += w*v0.x; z3.y += w*v0.y;
        }
    }
    float2* Zb = (float2*)g_Z;
    size_t o = (size_t)n*128;
    Zb[o + lane]      = z0;
    Zb[o + 32 + lane] = z1;
    Zb[o + 64 + lane] = z2;
    Zb[o + 96 + lane] = z3;
}

// ---------------- GAT per-node body, C=64: one float4/lane covers both heads ---
// lanes 0-15 carry head0 channels (4lh..4lh+3), lanes 16-31 carry head1.
__device__ __forceinline__ void gat_node64(int n, int lane, const float* __restrict__ h,
                                           const float* __restrict__ bias,
                                           float* __restrict__ Y, int relu) {
    int s = g_rowptr[n*RR];
    int t = g_rowptr[n*RR + RR];
    float2 dn  = ((const float2*)g_dn)[n];
    float2 snn = ((const float2*)g_sn)[n];
    int hd = lane >> 4, lh = lane & 15;
    const float4* hb = (const float4*)h;    // 32 float4 per row
    float den0l = 0.f, den1l = 0.f;
    float4 acc;
    {   // self-loop
        float e0 = __expf(leaky(snn.x + dn.x));
        float e1 = __expf(leaky(snn.y + dn.y));
        if (lane == 0) { den0l = e0; den1l = e1; }
        float f = hd ? e1 : e0;
        float4 v = hb[(size_t)n*32 + lane];
        acc.x = f*v.x; acc.y = f*v.y; acc.z = f*v.z; acc.w = f*v.w;
    }
    for (int base = s; base < t; base += 32) {
        int cnt = min(32, t - base);
        int pk = 0; float e0l = 0.f, e1l = 0.f;
        if (lane < cnt) {
            pk = g_epack[base + lane];
            float2 sv = ((const float2*)g_sn)[pk & 0xFFFF];
            e0l = __expf(leaky(sv.x + dn.x));
            e1l = __expf(leaky(sv.y + dn.y));
        }
        den0l += e0l; den1l += e1l;
        int j = 0;
        for (; j + 4 <= cnt; j += 4) {
#pragma unroll
            for (int u = 0; u < 4; u++) {
                int p    = __shfl_sync(FULLM, pk,  j+u);
                float f0 = __shfl_sync(FULLM, e0l, j+u);
                float f1 = __shfl_sync(FULLM, e1l, j+u);
                float f  = hd ? f1 : f0;
                float4 v = hb[(size_t)(p & 0xFFFF)*32 + lane];
                acc.x += f*v.x; acc.y += f*v.y; acc.z += f*v.z; acc.w += f*v.w;
            }
        }
        for (; j < cnt; j++) {
            int p    = __shfl_sync(FULLM, pk,  j);
            float f0 = __shfl_sync(FULLM, e0l, j);
            float f1 = __shfl_sync(FULLM, e1l, j);
            float f  = hd ? f1 : f0;
            float4 v = hb[(size_t)(p & 0xFFFF)*32 + lane];
            acc.x += f*v.x; acc.y += f*v.y; acc.z += f*v.z; acc.w += f*v.w;
        }
    }
#pragma unroll
    for (int off = 16; off; off >>= 1) {
        den0l += __shfl_xor_sync(FULLM, den0l, off);
        den1l += __shfl_xor_sync(FULLM, den1l, off);
    }
    float i0 = 1.f/den0l, i1 = 1.f/den1l;
    float4 oth;   // head1 acc down to lanes 0-15
    oth.x = __shfl_xor_sync(FULLM, acc.x, 16);
    oth.y = __shfl_xor_sync(FULLM, acc.y, 16);
    oth.z = __shfl_xor_sync(FULLM, acc.z, 16);
    oth.w = __shfl_xor_sync(FULLM, acc.w, 16);
    if (lane < 16) {
        float4 bv = ((const float4*)bias)[lh];
        float4 o;
        o.x = 0.5f*(acc.x*i0 + oth.x*i1) + bv.x;
        o.y = 0.5f*(acc.y*i0 + oth.y*i1) + bv.y;
        o.z = 0.5f*(acc.z*i0 + oth.z*i1) + bv.z;
        o.w = 0.5f*(acc.w*i0 + oth.w*i1) + bv.w;
        if (relu) {
            o.x = fmaxf(o.x, 0.f); o.y = fmaxf(o.y, 0.f);
            o.z = fmaxf(o.z, 0.f); o.w = fmaxf(o.w, 0.f);
        }
        ((float4*)Y)[(size_t)n*16 + lh] = o;
    }
}

// ---------------- GAT per-node body, generic C (used for C=16) ----------------
__device__ __forceinline__ void gat_node(int n, int lane, const float* __restrict__ h,
                                         const float* __restrict__ bias,
                                         float* __restrict__ Y, int C, int relu) {
    int s = g_rowptr[n*RR];
    int t = g_rowptr[n*RR + RR];
    float2 dn  = ((const float2*)g_dn)[n];
    float2 snn = ((const float2*)g_sn)[n];
    bool act = (2*lane < C);
    int C2 = C >> 1;
    const float2* hb = (const float2*)h;   // row stride = C float2
    float den0l = 0.f, den1l = 0.f;
    float2 acc0, acc1;
    {   // self-loop
        float e0 = __expf(leaky(snn.x + dn.x));
        float e1 = __expf(leaky(snn.y + dn.y));
        if (lane == 0) { den0l = e0; den1l = e1; }
        size_t ro = (size_t)n*C;
        float2 v0 = act ? hb[ro + lane]      : make_float2(0.f,0.f);
        float2 v1 = act ? hb[ro + C2 + lane] : make_float2(0.f,0.f);
        acc0 = make_float2(e0*v0.x, e0*v0.y);
        acc1 = make_float2(e1*v1.x, e1*v1.y);
    }
    for (int base = s; base < t; base += 32) {
        int cnt = min(32, t - base);
        int pk = 0; float e0l = 0.f, e1l = 0.f;
        if (lane < cnt) {
            pk = g_epack[base + lane];
            float2 sv = ((const float2*)g_sn)[pk & 0xFFFF];
            e0l = __expf(leaky(sv.x + dn.x));
            e1l = __expf(leaky(sv.y + dn.y));
        }
        den0l += e0l; den1l += e1l;
        for (int j = 0; j < cnt; j++) {
            int p    = __shfl_sync(FULLM, pk,  j);
            float f0 = __shfl_sync(FULLM, e0l, j);
            float f1 = __shfl_sync(FULLM, e1l, j);
            size_t r0 = (size_t)(p & 0xFFFF)*C;
            float2 zr = make_float2(0.f,0.f);
            float2 a0 = act ? hb[r0 + lane] : zr;
            float2 b0 = act ? hb[r0 + C2 + lane] : zr;
            acc0.x += f0*a0.x; acc0.y += f0*a0.y;
            acc1.x += f1*b0.x; acc1.y += f1*b0.y;
        }
    }
#pragma unroll
    for (int off = 16; off; off >>= 1) {
        den0l += __shfl_xor_sync(FULLM, den0l, off);
        den1l += __shfl_xor_sync(FULLM, den1l, off);
    }
    if (act) {
        float i0 = 1.f/den0l, i1 = 1.f/den1l;
        int c = 2*lane;
        float vx = 0.5f*(acc0.x*i0 + acc1.x*i1) + bias[c];
        float vy = 0.5f*(acc0.y*i0 + acc1.y*i1) + bias[c + 1];
        if (relu) { vx = fmaxf(vx, 0.f); vy = fmaxf(vy, 0.f); }
        Y[(size_t)n*C + c]     = vx;
        Y[(size_t)n*C + c + 1] = vy;
    }
}

// ---------------- fused per-layer aggregation: GAT warps first, then RGCN -----
__global__ void k_agg(const float* __restrict__ XR, const float* __restrict__ rc,
                      const float* __restrict__ h, const float* __restrict__ gb,
                      float* __restrict__ Yg, int C, int relu) {
    int gw = (blockIdx.x*blockDim.x + threadIdx.x) >> 5;
    int lane = threadIdx.x & 31;
    if (gw < NN) {
        if (C == 64) gat_node64(gw, lane, h, gb, Yg, relu);
        else         gat_node(gw, lane, h, gb, Yg, C, relu);
    } else if (gw < 2*NN) {
        rgcn_node(gw - NN, lane, XR, rc);
    }
}

// ---------------- TF32 tensor-core GEMM ----------------
__device__ __forceinline__ unsigned f2tf(float x) {
    unsigned r;
    asm("cvt.rna.tf32.f32 %0, %1;" : "=r"(r) : "f"(x));
    return r;
}
__device__ __forceinline__ void mma_tf32(float d[4], const unsigned a[4],
                                         const unsigned b[2], const float c[4]) {
    asm volatile(
        "mma.sync.aligned.m16n8k8.row.col.f32.tf32.tf32.f32 "
        "{%0,%1,%2,%3}, {%4,%5,%6,%7}, {%8,%9}, {%10,%11,%12,%13};\n"
        : "=f"(d[0]), "=f"(d[1]), "=f"(d[2]), "=f"(d[3])
        : "r"(a[0]), "r"(a[1]), "r"(a[2]), "r"(a[3]),
          "r"(b[0]), "r"(b[1]),
          "f"(c[0]), "f"(c[1]), "f"(c[2]), "f"(c[3]));
}

#define BM 128
#define BN 64
#define BK 32
#define KSTR (BK + 4)

__device__ __forceinline__ void ld_tileA(const float* __restrict__ A, int K, int M,
                                         int m0, int k0, int tid, float4 pa[4]) {
#pragma unroll
    for (int it = 0; it < 4; it++) {
        int idx = tid + it*256;
        int m = idx >> 3, kq = (idx & 7) << 2;
        int gm = m0 + m;
        pa[it] = (gm < M) ? *reinterpret_cast<const float4*>(&A[(size_t)gm*K + k0 + kq])
                          : make_float4(0.f,0.f,0.f,0.f);
    }
}
__device__ __forceinline__ void ld_tileB(const float* __restrict__ Bm, int NC,
                                         int n0, int k0, int tid, float pb[8]) {
#pragma unroll
    for (int it = 0; it < 8; it++) {
        int idx = tid + it*256;
        int k = idx >> 6, nn = idx & 63;
        int gn = n0 + nn;
        pb[it] = (gn < NC) ? Bm[(size_t)(k0 + k)*NC + gn] : 0.f;
    }
}

__device__ __forceinline__ void gemm_body(
    const float* __restrict__ A1, const float* __restrict__ B1, int K1,
    const float* __restrict__ A2, const float* __restrict__ B2, int K2,
    const float* __restrict__ bias, float* __restrict__ Y,
    int M, int NC, int relu, int bx, int by)
{
    __shared__ __align__(16) unsigned As[BM][KSTR];
    __shared__ __align__(16) unsigned Bs[BN][KSTR];
    int tid = threadIdx.x;
    int wid = tid >> 5, lane = tid & 31;
    int g = lane >> 2, t = lane & 3;
    int warp_m = (wid >> 1) * 32;
    int warp_n = (wid & 1) * 32;
    int m0 = by * BM, n0 = bx * BN;

    float acc[2][4][4] = {};
    float4 pa[4];
    float  pb[8];

    for (int pass = 0; pass < 2; pass++) {
        const float* A  = pass ? A2 : A1;
        const float* Bm = pass ? B2 : B1;
        int K = pass ? K2 : K1;
        if (K == 0 || A == nullptr) continue;
        ld_tileA(A, K, M, m0, 0, tid, pa);
        ld_tileB(Bm, NC, n0, 0, tid, pb);
        for (int k0 = 0; k0 < K; k0 += BK) {
#pragma unroll
            for (int it = 0; it < 4; it++) {
                int idx = tid + it*256;
                int m = idx >> 3, kq = (idx & 7) << 2;
                unsigned* p = &As[m][kq];
                p[0] = f2tf(pa[it].x); p[1] = f2tf(pa[it].y);
                p[2] = f2tf(pa[it].z); p[3] = f2tf(pa[it].w);
            }
#pragma unroll
            for (int it = 0; it < 8; it++) {
                int idx = tid + it*256;
                int k = idx >> 6, nn = idx & 63;
                Bs[nn][k] = f2tf(pb[it]);
            }
            __syncthreads();
            if (k0 + BK < K) {
                ld_tileA(A, K, M, m0, k0 + BK, tid, pa);
                ld_tileB(Bm, NC, n0, k0 + BK, tid, pb);
            }
#pragma unroll
            for (int kk = 0; kk < BK; kk += 8) {
                unsigned afr[2][4];
#pragma unroll
                for (int am = 0; am < 2; am++) {
                    int row = warp_m + am*16 + g;
                    afr[am][0] = As[row][kk + t];
                    afr[am][1] = As[row + 8][kk + t];
                    afr[am][2] = As[row][kk + t + 4];
                    afr[am][3] = As[row + 8][kk + t + 4];
                }
                unsigned bfr[4][2];
#pragma unroll
                for (int an = 0; an < 4; an++) {
                    int col = warp_n + an*8 + g;
                    bfr[an][0] = Bs[col][kk + t];
                    bfr[an][1] = Bs[col][kk + t + 4];
                }
#pragma unroll
                for (int am = 0; am < 2; am++)
#pragma unroll
                    for (int an = 0; an < 4; an++)
                        mma_tf32(acc[am][an], afr[am], bfr[an], acc[am][an]);
            }
            __syncthreads();
        }
    }
#pragma unroll
    for (int am = 0; am < 2; am++) {
#pragma unroll
        for (int an = 0; an < 4; an++) {
#pragma unroll
            for (int i = 0; i < 4; i++) {
                int row = warp_m + am*16 + g + (i >> 1)*8;
                int col = warp_n + an*8 + 2*t + (i & 1);
                int gm = m0 + row, gn = n0 + col;
                if (gm < M && gn < NC) {
                    float v = acc[am][an][i] + (bias ? bias[gn] : 0.f);
                    if (relu) v = fmaxf(v, 0.f);
                    Y[(size_t)gm*NC + gn] = v;
                }
            }
        }
    }
}

__global__ void k_gemm(const float* __restrict__ A1, const float* __restrict__ B1, int K1,
                       const float* __restrict__ A2, const float* __restrict__ B2, int K2,
                       const float* __restrict__ bias, float* __restrict__ Y,
                       int M, int NC, int relu)
{
    gemm_body(A1, B1, K1, A2, B2, K2, bias, Y, M, NC, relu, blockIdx.x, blockIdx.y);
}

// two independent GEMMs in one launch; blockIdx.z selects the problem.
__global__ void k_gemm_dual(
    const float* __restrict__ pA1, const float* __restrict__ pB1, int pK1,
    const float* __restrict__ pA2, const float* __restrict__ pB2, int pK2,
    const float* __restrict__ pbias, float* __restrict__ pY,
    int pM, int pNC, int prelu, int pGX,
    const float* __restrict__ qA1, const float* __restrict__ qB1, int qK1,
    const float* __restrict__ qA2, const float* __restrict__ qB2, int qK2,
    const float* __restrict__ qbias, float* __restrict__ qY,
    int qM, int qNC, int qrelu, int qGX)
{
    if (blockIdx.z == 0) {
        if ((int)blockIdx.x >= pGX) return;
        gemm_body(pA1, pB1, pK1, pA2, pB2, pK2, pbias, pY, pM, pNC, prelu,
                  blockIdx.x, blockIdx.y);
    } else {
        if ((int)blockIdx.x >= qGX) return;
        gemm_body(qA1, qB1, qK1, qA2, qB2, qK2, qbias, qY, qM, qNC, qrelu,
                  blockIdx.x, blockIdx.y);
    }
}

// ---- fused: gemm0 (x@gw0 -> h, NC=128) blocks, then scan_add blocks ----------
__global__ void k_sa_gemm0(const float* __restrict__ x, const float* __restrict__ gw0,
                           float* __restrict__ h, int gemmBlocks) {
    int bid = blockIdx.x;
    if (bid < gemmBlocks) {
        gemm_body(x, gw0, 64, nullptr, nullptr, 0, nullptr, h, NN, 128, 0,
                  bid & 1, bid >> 1);
    } else {
        int i = (bid - gemmBlocks)*blockDim.x + threadIdx.x;
        if (i < NR) {
            int v = g_rowptr[i+1] + g_boff[i >> 10];
            g_rowptr[i+1] = v;
            if (i + 1 < NR) g_cur[i+1] = v;
        }
        if (i == 0) { g_rowptr[0] = 0; g_cur[0] = 0; }
    }
}

// ---- fused: fill blocks, then attdot0 blocks ---------------------------------
__global__ void k_fill_attdot(const int* __restrict__ ei, const int* __restrict__ et,
                              int fillBlocks, const float* __restrict__ h,
                              const float* __restrict__ gas, const float* __restrict__ gad,
                              int C) {
    int bid = blockIdx.x;
    if (bid < fillBlocks) {
        int e = bid*blockDim.x + threadIdx.x;
        if (e >= EE) return;
        int src = ei[e];
        int dst = ei[EE + e];
        int r   = et[e];
        int p = atomicAdd(&g_cur[dst*RR + r], 1);
        g_epack[p] = src | (r << 16);
    } else {
        int gw = ((bid - fillBlocks)*blockDim.x + threadIdx.x) >> 5;
        int lane = threadIdx.x & 31;
        if (gw >= NN) return;
        int C2 = C >> 1;
        const float2* hb = (const float2*)h;
        const float2* gs = (const float2*)gas;
        const float2* gd = (const float2*)gad;
        size_t ro = (size_t)gw*C;
        float s0 = 0.f, d0 = 0.f, s1 = 0.f, d1 = 0.f;
        for (int i = lane; i < C2; i += 32) {
            float2 v0 = hb[ro + i], v1 = hb[ro + C2 + i];
            float2 a0 = gs[i], a1 = gs[C2 + i];
            float2 b0 = gd[i], b1 = gd[C2 + i];
            s0 += v0.x*a0.x + v0.y*a0.y;  d0 += v0.x*b0.x + v0.y*b0.y;
            s1 += v1.x*a1.x + v1.y*a1.y;  d1 += v1.x*b1.x + v1.y*b1.y;
        }
#pragma unroll
        for (int off = 16; off; off >>= 1) {
            s0 += __shfl_xor_sync(FULLM, s0, off);
            d0 += __shfl_xor_sync(FULLM, d0, off);
            s1 += __shfl_xor_sync(FULLM, s1, off);
            d1 += __shfl_xor_sync(FULLM, d1, off);
        }
        if (lane == 0) {
            ((float2*)g_sn)[gw] = make_float2(s0, s1);
            ((float2*)g_dn)[gw] = make_float2(d0, d1);
        }
    }
}

// ---------------- attention dots: warp per node, coalesced ----------------
__global__ void k_attdot(const float* __restrict__ h, const float* __restrict__ gas,
                         const float* __restrict__ gad, int C) {
    int gw = (blockIdx.x*blockDim.x + threadIdx.x) >> 5;
    int lane = threadIdx.x & 31;
    if (gw >= NN) return;
    int C2 = C >> 1;
    const float2* hb = (const float2*)h;
    const float2* gs = (const float2*)gas;
    const float2* gd = (const float2*)gad;
    size_t ro = (size_t)gw*C;
    float s0 = 0.f, d0 = 0.f, s1 = 0.f, d1 = 0.f;
    for (int i = lane; i < C2; i += 32) {
        float2 v0 = hb[ro + i], v1 = hb[ro + C2 + i];
        float2 a0 = gs[i], a1 = gs[C2 + i];
        float2 b0 = gd[i], b1 = gd[C2 + i];
        s0 += v0.x*a0.x + v0.y*a0.y;  d0 += v0.x*b0.x + v0.y*b0.y;
        s1 += v1.x*a1.x + v1.y*a1.y;  d1 += v1.x*b1.x + v1.y*b1.y;
    }
#pragma unroll
    for (int off = 16; off; off >>= 1) {
        s0 += __shfl_xor_sync(FULLM, s0, off);
        d0 += __shfl_xor_sync(FULLM, d0, off);
        s1 += __shfl_xor_sync(FULLM, s1, off);
        d1 += __shfl_xor_sync(FULLM, d1, off);
    }
    if (lane == 0) {
        ((float2*)g_sn)[gw] = make_float2(s0, s1);
        ((float2*)g_dn)[gw] = make_float2(d0, d1);
    }
}

// ---------------- final combine ----------------
__global__ void k_final(const float* __restrict__ y1, const float* __restrict__ y2,
                        float* __restrict__ out) {
    int n = blockIdx.x*blockDim.x + threadIdx.x;
    if (n >= NN) return;
    float m = 0.f;
#pragma unroll
    for (int c = 0; c < 16; c++) m += y2[(size_t)n*16 + c];
    m *= (1.f/16.f);
#pragma unroll
    for (int c = 0; c < 16; c++)
        out[(size_t)n*16 + c] = tanhf(y1[(size_t)n*16 + c] + m);
}

// ---------------- host ----------------
extern "C" void kernel_launch(void* const* d_in, const int* in_sizes, int n_in,
                              void* d_out, int out_size) {
    const float* x  = (const float*)d_in[0];
    const int*   ei = (const int*)d_in[1];
    const int*   et = (const int*)d_in[2];
    const float *rb[3], *rc[3], *rrw[3], *rbias[3], *gw[3], *gas[3], *gad[3], *gb[3];
    for (int k = 0; k < 3; k++) {
        int base = 3 + k*8;
        rb[k]    = (const float*)d_in[base + 0];
        rc[k]    = (const float*)d_in[base + 1];
        rrw[k]   = (const float*)d_in[base + 2];
        rbias[k] = (const float*)d_in[base + 3];
        gw[k]    = (const float*)d_in[base + 4];
        gas[k]   = (const float*)d_in[base + 5];
        gad[k]   = (const float*)d_in[base + 6];
        gb[k]    = (const float*)d_in[base + 7];
    }
    float* out = (float*)d_out;

    float *Z, *h, *A, *Bf, *C, *D; int* degp;
    cudaGetSymbolAddress((void**)&Z, g_Z);
    cudaGetSymbolAddress((void**)&h, g_h);
    cudaGetSymbolAddress((void**)&A, g_bufA);
    cudaGetSymbolAddress((void**)&Bf, g_bufB);
    cudaGetSymbolAddress((void**)&C, g_bufC);
    cudaGetSymbolAddress((void**)&D, g_bufD);
    cudaGetSymbolAddress((void**)&degp, g_deg);

    dim3 blk(256);
    dim3 grid64((64  + BN - 1)/BN, (NN + BM - 1)/BM);
    dim3 grid16((16  + BN - 1)/BN, (NN + BM - 1)/BM);
    dim3 grid32((32  + BN - 1)/BN, (NN + BM - 1)/BM);
    int aggGrid  = ((2*NN)*32 + 255)/256;
    int wGrid    = (NN*32 + 255)/256;       // 6250
    int gy       = (NN + BM - 1)/BM;        // 391
    int gemm0B   = 2*gy;                    // 782 (NC=128, gx=2)
    int saB      = (NR + 255)/256;          // 1563
    int fillB    = (EE + 255)/256;          // 3125

    // ---- CSR build + GAT-0 projection/attdot, fused to cut launch count ----
    cudaMemsetAsync(degp, 0, NR*sizeof(int), 0);
    k_hist<<<(EE + 255)/256, 256>>>(ei, et);
    k_scan_block<<<(NR + 1023)/1024, 1024>>>();
    k_sa_gemm0<<<gemm0B + saB, blk>>>(x, gw[0], h, gemm0B);          // gemm0 || scan_add
    k_fill_attdot<<<fillB + wGrid, blk>>>(ei, et, fillB, h, gas[0], gad[0], 64);

    // ---- layer 0: fused agg (gat h -> Bf, rgcn x -> Z) ----
    k_agg<<<aggGrid, 256>>>(x, rc[0], h, gb[0], Bf, 64, 1);
    // dual: rgcn0 GEMM (Z,rb0 + x,rr0 -> A)  ||  gat1 projection (Bf,gw1 -> h)
    {
        dim3 dgrid(2, gy, 2);
        k_gemm_dual<<<dgrid, blk>>>(
            Z, rb[0], BB*64, x, rrw[0], 64, rbias[0], A, NN, 64, 1, 1,
            Bf, gw[1], 64, nullptr, nullptr, 0, nullptr, h, NN, 128, 0, 2);
    }
    k_attdot<<<wGrid, 256>>>(h, gas[1], gad[1], 64);

    // ---- layer 1 agg + rgcn1 GEMM ----
    k_agg<<<aggGrid, 256>>>(A, rc[1], h, gb[1], D, 64, 1);
    k_gemm<<<grid64, blk>>>(Z, rb[1], BB*64, A, rrw[1], 64, rbias[1], C, NN, 64, 1);

    // ---- swap: rgcn gets GAT branch (D), gat gets RGCN branch (C) ----
    k_gemm<<<grid32, blk>>>(C, gw[2], 64, nullptr, nullptr, 0, nullptr, h, NN, 32, 0);
    k_attdot<<<wGrid, 256>>>(h, gas[2], gad[2], 16);
    k_agg<<<aggGrid, 256>>>(D, rc[2], h, gb[2], Bf, 16, 0);
    k_gemm<<<grid16, blk>>>(Z, rb[2], BB*64, D, rrw[2], 64, rbias[2], A, NN, 16, 0);

    // ---- combine ----
    k_final<<<(NN + 255)/256, 256>>>(A, Bf, out);
}

// round 13
// speedup vs baseline: 1.0225x; 1.0225x over previous
#include <cuda_runtime.h>
#include <math.h>

#define NN 50000
#define EE 800000
#define RR 8
#define BB 4
#define NHH 2
#define NR (NN*RR)   // 400000
#define NEG 0.2f
#define FULLM 0xFFFFFFFFu

// ---------------- device scratch ----------------
__device__ int g_deg[NR];        // zero at module load; re-zeroed by k_final each replay
__device__ int g_rowptr[NR+1];
__device__ int g_cur[NR];
__device__ int g_epack[EE];      // src | (rel << 16)
__device__ int g_bsum[512];
__device__ int g_boff[512];
__device__ int g_ctr;

__device__ float g_Z[(size_t)NN*BB*64];   // RGCN basis-folded aggregates [N, 256]
__device__ float g_h[(size_t)NN*NHH*64];  // GAT projected features
__device__ float g_sn[NN*NHH];            // att_src dot (float2-viewable)
__device__ float g_dn[NN*NHH];            // att_dst dot
__device__ float g_bufA[(size_t)NN*64];
__device__ float g_bufB[(size_t)NN*64];
__device__ float g_bufC[(size_t)NN*64];
__device__ float g_bufD[(size_t)NN*64];

// ---------------- CSR build ----------------
__global__ void k_hist(const int* __restrict__ ei, const int* __restrict__ et) {
    int e = blockIdx.x*blockDim.x + threadIdx.x;
    if (e >= EE) return;
    int dst = ei[EE + e];
    int r   = et[e];
    atomicAdd(&g_deg[dst*RR + r], 1);
}
// block scan; LAST finishing block also scans per-block sums AND self-resets g_ctr
__global__ void k_scan_block() { // 1024 threads/block
    __shared__ int sh[1024];
    __shared__ bool isLast;
    int i = blockIdx.x*1024 + threadIdx.x;
    int v = (i < NR) ? g_deg[i] : 0;
    sh[threadIdx.x] = v;
    __syncthreads();
    for (int off = 1; off < 1024; off <<= 1) {
        int t = (threadIdx.x >= off) ? sh[threadIdx.x - off] : 0;
        __syncthreads();
        sh[threadIdx.x] += t;
        __syncthreads();
    }
    if (i < NR) g_rowptr[i+1] = sh[threadIdx.x];
    if (threadIdx.x == 1023) g_bsum[blockIdx.x] = sh[1023];
    __threadfence();
    if (threadIdx.x == 0) isLast = (atomicAdd(&g_ctr, 1) == (int)gridDim.x - 1);
    __syncthreads();
    if (!isLast) return;
    int nb = gridDim.x;
    int v2 = (threadIdx.x < 512 && (int)threadIdx.x < nb) ? g_bsum[threadIdx.x] : 0;
    __syncthreads();
    if (threadIdx.x < 512) sh[threadIdx.x] = v2;
    __syncthreads();
    for (int off = 1; off < 512; off <<= 1) {
        int t = (threadIdx.x < 512 && threadIdx.x >= (unsigned)off) ? sh[threadIdx.x - off] : 0;
        __syncthreads();
        if (threadIdx.x < 512) sh[threadIdx.x] += t;
        __syncthreads();
    }
    if ((int)threadIdx.x < nb) g_boff[threadIdx.x] = sh[threadIdx.x] - v2; // exclusive
    if (threadIdx.x == 0) g_ctr = 0;   // self-reset for next graph replay
}

__device__ __forceinline__ float leaky(float v) { return v > 0.f ? v : NEG*v; }

// ---------------- RGCN per-node body (R9-proven: float2, MLP-batched) ----------
__device__ __forceinline__ void rgcn_node(int n, int lane, const float* __restrict__ X,
                                          const float* __restrict__ rc) {
    int rp = 0;
    if (lane <= 8) rp = g_rowptr[n*RR + lane];
    int s   = __shfl_sync(FULLM, rp, 0);
    int e8  = __shfl_sync(FULLM, rp, 8);
    int deg = e8 - s;
    int nxt = __shfl_down_sync(FULLM, rp, 1);
    int cseg = nxt - rp;
    float invr = (lane < 8 && cseg > 0) ? 1.0f/(float)cseg : 0.f;
    float rcw = rc[lane] * __shfl_sync(FULLM, invr, lane >> 2);
    float2 z0 = {0.f,0.f}, z1 = {0.f,0.f}, z2 = {0.f,0.f}, z3 = {0.f,0.f};
    const float2* Xb = (const float2*)X;
    for (int base = 0; base < deg; base += 32) {
        int cnt = min(32, deg - base);
        int pk = (lane < cnt) ? g_epack[s + base + lane] : 0;
        int j = 0;
        for (; j + 4 <= cnt; j += 4) {
            int p0 = __shfl_sync(FULLM, pk, j);
            int p1 = __shfl_sync(FULLM, pk, j+1);
            int p2 = __shfl_sync(FULLM, pk, j+2);
            int p3 = __shfl_sync(FULLM, pk, j+3);
            float2 v0 = Xb[(size_t)(p0 & 0xFFFF)*32 + lane];
            float2 v1 = Xb[(size_t)(p1 & 0xFFFF)*32 + lane];
            float2 v2 = Xb[(size_t)(p2 & 0xFFFF)*32 + lane];
            float2 v3 = Xb[(size_t)(p3 & 0xFFFF)*32 + lane];
            int r0 = (p0 >> 16) << 2, r1 = (p1 >> 16) << 2;
            int r2 = (p2 >> 16) << 2, r3 = (p3 >> 16) << 2;
            float w;
            w = __shfl_sync(FULLM, rcw, r0+0); z0.x += w*v0.x; z0.y += w*v0.y;
            w = __shfl_sync(FULLM, rcw, r0+1); z1.x += w*v0.x; z1.y += w*v0.y;
            w = __shfl_sync(FULLM, rcw, r0+2); z2.x += w*v0.x; z2.y += w*v0.y;
            w = __shfl_sync(FULLM, rcw, r0+3); z3.x += w*v0.x; z3.y += w*v0.y;
            w = __shfl_sync(FULLM, rcw, r1+0); z0.x += w*v1.x; z0.y += w*v1.y;
            w = __shfl_sync(FULLM, rcw, r1+1); z1.x += w*v1.x; z1.y += w*v1.y;
            w = __shfl_sync(FULLM, rcw, r1+2); z2.x += w*v1.x; z2.y += w*v1.y;
            w = __shfl_sync(FULLM, rcw, r1+3); z3.x += w*v1.x; z3.y += w*v1.y;
            w = __shfl_sync(FULLM, rcw, r2+0); z0.x += w*v2.x; z0.y += w*v2.y;
            w = __shfl_sync(FULLM, rcw, r2+1); z1.x += w*v2.x; z1.y += w*v2.y;
            w = __shfl_sync(FULLM, rcw, r2+2); z2.x += w*v2.x; z2.y += w*v2.y;
            w = __shfl_sync(FULLM, rcw, r2+3); z3.x += w*v2.x; z3.y += w*v2.y;
            w = __shfl_sync(FULLM, rcw, r3+0); z0.x += w*v3.x; z0.y += w*v3.y;
            w = __shfl_sync(FULLM, rcw, r3+1); z1.x += w*v3.x; z1.y += w*v3.y;
            w = __shfl_sync(FULLM, rcw, r3+2); z2.x += w*v3.x; z2.y += w*v3.y;
            w = __shfl_sync(FULLM, rcw, r3+3); z3.x += w*v3.x; z3.y += w*v3.y;
        }
        for (; j < cnt; j++) {
            int p0 = __shfl_sync(FULLM, pk, j);
            float2 v0 = Xb[(size_t)(p0 & 0xFFFF)*32 + lane];
            int r0 = (p0 >> 16) << 2;
            float w;
            w = __shfl_sync(FULLM, rcw, r0+0); z0.x += w*v0.x; z0.y += w*v0.y;
            w = __shfl_sync(FULLM, rcw, r0+1); z1.x += w*v0.x; z1.y += w*v0.y;
            w = __shfl_sync(FULLM, rcw, r0+2); z2.x += w*v0.x; z2.y += w*v0.y;
            w = __shfl_sync(FULLM, rcw, r0+3); z3.x += w*v0.x; z3.y += w*v0.y;
        }
    }
    float2* Zb = (float2*)g_Z;
    size_t o = (size_t)n*128;
    Zb[o + lane]      = z0;
    Zb[o + 32 + lane] = z1;
    Zb[o + 64 + lane] = z2;
    Zb[o + 96 + lane] = z3;
}

// ---------------- GAT per-node body (R5-proven: single-pass, no max shift) -----
__device__ __forceinline__ void gat_node(int n, int lane, const float* __restrict__ h,
                                         const float* __restrict__ bias,
                                         float* __restrict__ Y, int C, int relu) {
    int s = g_rowptr[n*RR];
    int t = g_rowptr[n*RR + RR];
    float2 dn  = ((const float2*)g_dn)[n];
    float2 snn = ((const float2*)g_sn)[n];
    bool act = (2*lane < C);
    int C2 = C >> 1;
    const float2* hb = (const float2*)h;   // row stride = C float2
    float den0l = 0.f, den1l = 0.f;
    float2 acc0, acc1;
    {   // self-loop
        float e0 = __expf(leaky(snn.x + dn.x));
        float e1 = __expf(leaky(snn.y + dn.y));
        if (lane == 0) { den0l = e0; den1l = e1; }
        size_t ro = (size_t)n*C;
        float2 v0 = act ? hb[ro + lane]      : make_float2(0.f,0.f);
        float2 v1 = act ? hb[ro + C2 + lane] : make_float2(0.f,0.f);
        acc0 = make_float2(e0*v0.x, e0*v0.y);
        acc1 = make_float2(e1*v1.x, e1*v1.y);
    }
    for (int base = s; base < t; base += 32) {
        int cnt = min(32, t - base);
        int pk = 0; float e0l = 0.f, e1l = 0.f;
        if (lane < cnt) {
            pk = g_epack[base + lane];
            float2 sv = ((const float2*)g_sn)[pk & 0xFFFF];
            e0l = __expf(leaky(sv.x + dn.x));
            e1l = __expf(leaky(sv.y + dn.y));
        }
        den0l += e0l; den1l += e1l;
        int j = 0;
        for (; j + 4 <= cnt; j += 4) {
            int p0 = __shfl_sync(FULLM, pk, j);
            int p1 = __shfl_sync(FULLM, pk, j+1);
            int p2 = __shfl_sync(FULLM, pk, j+2);
            int p3 = __shfl_sync(FULLM, pk, j+3);
            float f00 = __shfl_sync(FULLM, e0l, j),   f10 = __shfl_sync(FULLM, e1l, j);
            float f01 = __shfl_sync(FULLM, e0l, j+1), f11 = __shfl_sync(FULLM, e1l, j+1);
            float f02 = __shfl_sync(FULLM, e0l, j+2), f12 = __shfl_sync(FULLM, e1l, j+2);
            float f03 = __shfl_sync(FULLM, e0l, j+3), f13 = __shfl_sync(FULLM, e1l, j+3);
            size_t r0 = (size_t)(p0 & 0xFFFF)*C, r1 = (size_t)(p1 & 0xFFFF)*C;
            size_t r2 = (size_t)(p2 & 0xFFFF)*C, r3 = (size_t)(p3 & 0xFFFF)*C;
            float2 zr = make_float2(0.f,0.f);
            float2 a0 = act ? hb[r0 + lane] : zr, b0 = act ? hb[r0 + C2 + lane] : zr;
            float2 a1 = act ? hb[r1 + lane] : zr, b1 = act ? hb[r1 + C2 + lane] : zr;
            float2 a2 = act ? hb[r2 + lane] : zr, b2 = act ? hb[r2 + C2 + lane] : zr;
            float2 a3 = act ? hb[r3 + lane] : zr, b3 = act ? hb[r3 + C2 + lane] : zr;
            acc0.x += f00*a0.x; acc0.y += f00*a0.y; acc1.x += f10*b0.x; acc1.y += f10*b0.y;
            acc0.x += f01*a1.x; acc0.y += f01*a1.y; acc1.x += f11*b1.x; acc1.y += f11*b1.y;
            acc0.x += f02*a2.x; acc0.y += f02*a2.y; acc1.x += f12*b2.x; acc1.y += f12*b2.y;
            acc0.x += f03*a3.x; acc0.y += f03*a3.y; acc1.x += f13*b3.x; acc1.y += f13*b3.y;
        }
        for (; j < cnt; j++) {
            int p0 = __shfl_sync(FULLM, pk, j);
            float f0 = __shfl_sync(FULLM, e0l, j), f1 = __shfl_sync(FULLM, e1l, j);
            size_t r0 = (size_t)(p0 & 0xFFFF)*C;
            float2 zr = make_float2(0.f,0.f);
            float2 a0 = act ? hb[r0 + lane] : zr, b0 = act ? hb[r0 + C2 + lane] : zr;
            acc0.x += f0*a0.x; acc0.y += f0*a0.y;
            acc1.x += f1*b0.x; acc1.y += f1*b0.y;
        }
    }
#pragma unroll
    for (int off = 16; off; off >>= 1) {
        den0l += __shfl_xor_sync(FULLM, den0l, off);
        den1l += __shfl_xor_sync(FULLM, den1l, off);
    }
    if (act) {
        float i0 = 1.f/den0l, i1 = 1.f/den1l;
        int c = 2*lane;
        float vx = 0.5f*(acc0.x*i0 + acc1.x*i1) + bias[c];
        float vy = 0.5f*(acc0.y*i0 + acc1.y*i1) + bias[c + 1];
        if (relu) { vx = fmaxf(vx, 0.f); vy = fmaxf(vy, 0.f); }
        Y[(size_t)n*C + c]     = vx;
        Y[(size_t)n*C + c + 1] = vy;
    }
}

// ---------------- fused per-layer aggregation: GAT warps first, then RGCN -----
__global__ void k_agg(const float* __restrict__ XR, const float* __restrict__ rc,
                      const float* __restrict__ h, const float* __restrict__ gb,
                      float* __restrict__ Yg, int C, int relu) {
    int gw = (blockIdx.x*blockDim.x + threadIdx.x) >> 5;
    int lane = threadIdx.x & 31;
    if (gw < NN)          gat_node(gw, lane, h, gb, Yg, C, relu);
    else if (gw < 2*NN)   rgcn_node(gw - NN, lane, XR, rc);
}

// ---------------- TF32 tensor-core GEMM ----------------
__device__ __forceinline__ unsigned f2tf(float x) {
    unsigned r;
    asm("cvt.rna.tf32.f32 %0, %1;" : "=r"(r) : "f"(x));
    return r;
}
__device__ __forceinline__ void mma_tf32(float d[4], const unsigned a[4],
                                         const unsigned b[2], const float c[4]) {
    asm volatile(
        "mma.sync.aligned.m16n8k8.row.col.f32.tf32.tf32.f32 "
        "{%0,%1,%2,%3}, {%4,%5,%6,%7}, {%8,%9}, {%10,%11,%12,%13};\n"
        : "=f"(d[0]), "=f"(d[1]), "=f"(d[2]), "=f"(d[3])
        : "r"(a[0]), "r"(a[1]), "r"(a[2]), "r"(a[3]),
          "r"(b[0]), "r"(b[1]),
          "f"(c[0]), "f"(c[1]), "f"(c[2]), "f"(c[3]));
}

#define BM 128
#define BN 64
#define BK 32
#define KSTR (BK + 4)

__device__ __forceinline__ void ld_tileA(const float* __restrict__ A, int K, int M,
                                         int m0, int k0, int tid, float4 pa[4]) {
#pragma unroll
    for (int it = 0; it < 4; it++) {
        int idx = tid + it*256;
        int m = idx >> 3, kq = (idx & 7) << 2;
        int gm = m0 + m;
        pa[it] = (gm < M) ? *reinterpret_cast<const float4*>(&A[(size_t)gm*K + k0 + kq])
                          : make_float4(0.f,0.f,0.f,0.f);
    }
}
__device__ __forceinline__ void ld_tileB(const float* __restrict__ Bm, int NC,
                                         int n0, int k0, int tid, float pb[8]) {
#pragma unroll
    for (int it = 0; it < 8; it++) {
        int idx = tid + it*256;
        int k = idx >> 6, nn = idx & 63;
        int gn = n0 + nn;
        pb[it] = (gn < NC) ? Bm[(size_t)(k0 + k)*NC + gn] : 0.f;
    }
}

__device__ __forceinline__ void gemm_body(
    const float* __restrict__ A1, const float* __restrict__ B1, int K1,
    const float* __restrict__ A2, const float* __restrict__ B2, int K2,
    const float* __restrict__ bias, float* __restrict__ Y,
    int M, int NC, int relu, int bx, int by)
{
    __shared__ __align__(16) unsigned As[BM][KSTR];
    __shared__ __align__(16) unsigned Bs[BN][KSTR];
    int tid = threadIdx.x;
    int wid = tid >> 5, lane = tid & 31;
    int g = lane >> 2, t = lane & 3;
    int warp_m = (wid >> 1) * 32;
    int warp_n = (wid & 1) * 32;
    int m0 = by * BM, n0 = bx * BN;

    float acc[2][4][4] = {};
    float4 pa[4];
    float  pb[8];

    for (int pass = 0; pass < 2; pass++) {
        const float* A  = pass ? A2 : A1;
        const float* Bm = pass ? B2 : B1;
        int K = pass ? K2 : K1;
        if (K == 0 || A == nullptr) continue;
        ld_tileA(A, K, M, m0, 0, tid, pa);
        ld_tileB(Bm, NC, n0, 0, tid, pb);
        for (int k0 = 0; k0 < K; k0 += BK) {
#pragma unroll
            for (int it = 0; it < 4; it++) {
                int idx = tid + it*256;
                int m = idx >> 3, kq = (idx & 7) << 2;
                unsigned* p = &As[m][kq];
                p[0] = f2tf(pa[it].x); p[1] = f2tf(pa[it].y);
                p[2] = f2tf(pa[it].z); p[3] = f2tf(pa[it].w);
            }
#pragma unroll
            for (int it = 0; it < 8; it++) {
                int idx = tid + it*256;
                int k = idx >> 6, nn = idx & 63;
                Bs[nn][k] = f2tf(pb[it]);
            }
            __syncthreads();
            if (k0 + BK < K) {
                ld_tileA(A, K, M, m0, k0 + BK, tid, pa);
                ld_tileB(Bm, NC, n0, k0 + BK, tid, pb);
            }
#pragma unroll
            for (int kk = 0; kk < BK; kk += 8) {
                unsigned afr[2][4];
#pragma unroll
                for (int am = 0; am < 2; am++) {
                    int row = warp_m + am*16 + g;
                    afr[am][0] = As[row][kk + t];
                    afr[am][1] = As[row + 8][kk + t];
                    afr[am][2] = As[row][kk + t + 4];
                    afr[am][3] = As[row + 8][kk + t + 4];
                }
                unsigned bfr[4][2];
#pragma unroll
                for (int an = 0; an < 4; an++) {
                    int col = warp_n + an*8 + g;
                    bfr[an][0] = Bs[col][kk + t];
                    bfr[an][1] = Bs[col][kk + t + 4];
                }
#pragma unroll
                for (int am = 0; am < 2; am++)
#pragma unroll
                    for (int an = 0; an < 4; an++)
                        mma_tf32(acc[am][an], afr[am], bfr[an], acc[am][an]);
            }
            __syncthreads();
        }
    }
#pragma unroll
    for (int am = 0; am < 2; am++) {
#pragma unroll
        for (int an = 0; an < 4; an++) {
#pragma unroll
            for (int i = 0; i < 4; i++) {
                int row = warp_m + am*16 + g + (i >> 1)*8;
                int col = warp_n + an*8 + 2*t + (i & 1);
                int gm = m0 + row, gn = n0 + col;
                if (gm < M && gn < NC) {
                    float v = acc[am][an][i] + (bias ? bias[gn] : 0.f);
                    if (relu) v = fmaxf(v, 0.f);
                    Y[(size_t)gm*NC + gn] = v;
                }
            }
        }
    }
}

__global__ void k_gemm(const float* __restrict__ A1, const float* __restrict__ B1, int K1,
                       const float* __restrict__ A2, const float* __restrict__ B2, int K2,
                       const float* __restrict__ bias, float* __restrict__ Y,
                       int M, int NC, int relu)
{
    gemm_body(A1, B1, K1, A2, B2, K2, bias, Y, M, NC, relu, blockIdx.x, blockIdx.y);
}

// two independent GEMMs in one launch; blockIdx.z selects the problem.
__global__ void k_gemm_dual(
    const float* __restrict__ pA1, const float* __restrict__ pB1, int pK1,
    const float* __restrict__ pA2, const float* __restrict__ pB2, int pK2,
    const float* __restrict__ pbias, float* __restrict__ pY,
    int pM, int pNC, int prelu, int pGX,
    const float* __restrict__ qA1, const float* __restrict__ qB1, int qK1,
    const float* __restrict__ qA2, const float* __restrict__ qB2, int qK2,
    const float* __restrict__ qbias, float* __restrict__ qY,
    int qM, int qNC, int qrelu, int qGX)
{
    if (blockIdx.z == 0) {
        if ((int)blockIdx.x >= pGX) return;
        gemm_body(pA1, pB1, pK1, pA2, pB2, pK2, pbias, pY, pM, pNC, prelu,
                  blockIdx.x, blockIdx.y);
    } else {
        if ((int)blockIdx.x >= qGX) return;
        gemm_body(qA1, qB1, qK1, qA2, qB2, qK2, qbias, qY, qM, qNC, qrelu,
                  blockIdx.x, blockIdx.y);
    }
}

// ---- fused: gemm0 (x@gw0 -> h, NC=128) blocks, then scan_add blocks ----------
__global__ void k_sa_gemm0(const float* __restrict__ x, const float* __restrict__ gw0,
                           float* __restrict__ h, int gemmBlocks) {
    int bid = blockIdx.x;
    if (bid < gemmBlocks) {
        gemm_body(x, gw0, 64, nullptr, nullptr, 0, nullptr, h, NN, 128, 0,
                  bid & 1, bid >> 1);
    } else {
        int i = (bid - gemmBlocks)*blockDim.x + threadIdx.x;
        if (i < NR) {
            int v = g_rowptr[i+1] + g_boff[i >> 10];
            g_rowptr[i+1] = v;
            if (i + 1 < NR) g_cur[i+1] = v;
        }
        if (i == 0) { g_rowptr[0] = 0; g_cur[0] = 0; }
    }
}

// ---- fused: fill blocks, then attdot0 blocks ---------------------------------
__global__ void k_fill_attdot(const int* __restrict__ ei, const int* __restrict__ et,
                              int fillBlocks, const float* __restrict__ h,
                              const float* __restrict__ gas, const float* __restrict__ gad,
                              int C) {
    int bid = blockIdx.x;
    if (bid < fillBlocks) {
        int e = bid*blockDim.x + threadIdx.x;
        if (e >= EE) return;
        int src = ei[e];
        int dst = ei[EE + e];
        int r   = et[e];
        int p = atomicAdd(&g_cur[dst*RR + r], 1);
        g_epack[p] = src | (r << 16);
    } else {
        int gw = ((bid - fillBlocks)*blockDim.x + threadIdx.x) >> 5;
        int lane = threadIdx.x & 31;
        if (gw >= NN) return;
        int C2 = C >> 1;
        const float2* hb = (const float2*)h;
        const float2* gs = (const float2*)gas;
        const float2* gd = (const float2*)gad;
        size_t ro = (size_t)gw*C;
        float s0 = 0.f, d0 = 0.f, s1 = 0.f, d1 = 0.f;
        for (int i = lane; i < C2; i += 32) {
            float2 v0 = hb[ro + i], v1 = hb[ro + C2 + i];
            float2 a0 = gs[i], a1 = gs[C2 + i];
            float2 b0 = gd[i], b1 = gd[C2 + i];
            s0 += v0.x*a0.x + v0.y*a0.y;  d0 += v0.x*b0.x + v0.y*b0.y;
            s1 += v1.x*a1.x + v1.y*a1.y;  d1 += v1.x*b1.x + v1.y*b1.y;
        }
#pragma unroll
        for (int off = 16; off; off >>= 1) {
            s0 += __shfl_xor_sync(FULLM, s0, off);
            d0 += __shfl_xor_sync(FULLM, d0, off);
            s1 += __shfl_xor_sync(FULLM, s1, off);
            d1 += __shfl_xor_sync(FULLM, d1, off);
        }
        if (lane == 0) {
            ((float2*)g_sn)[gw] = make_float2(s0, s1);
            ((float2*)g_dn)[gw] = make_float2(d0, d1);
        }
    }
}

// ---------------- attention dots: warp per node, coalesced ----------------
__global__ void k_attdot(const float* __restrict__ h, const float* __restrict__ gas,
                         const float* __restrict__ gad, int C) {
    int gw = (blockIdx.x*blockDim.x + threadIdx.x) >> 5;
    int lane = threadIdx.x & 31;
    if (gw >= NN) return;
    int C2 = C >> 1;
    const float2* hb = (const float2*)h;
    const float2* gs = (const float2*)gas;
    const float2* gd = (const float2*)gad;
    size_t ro = (size_t)gw*C;
    float s0 = 0.f, d0 = 0.f, s1 = 0.f, d1 = 0.f;
    for (int i = lane; i < C2; i += 32) {
        float2 v0 = hb[ro + i], v1 = hb[ro + C2 + i];
        float2 a0 = gs[i], a1 = gs[C2 + i];
        float2 b0 = gd[i], b1 = gd[C2 + i];
        s0 += v0.x*a0.x + v0.y*a0.y;  d0 += v0.x*b0.x + v0.y*b0.y;
        s1 += v1.x*a1.x + v1.y*a1.y;  d1 += v1.x*b1.x + v1.y*b1.y;
    }
#pragma unroll
    for (int off = 16; off; off >>= 1) {
        s0 += __shfl_xor_sync(FULLM, s0, off);
        d0 += __shfl_xor_sync(FULLM, d0, off);
        s1 += __shfl_xor_sync(FULLM, s1, off);
        d1 += __shfl_xor_sync(FULLM, d1, off);
    }
    if (lane == 0) {
        ((float2*)g_sn)[gw] = make_float2(s0, s1);
        ((float2*)g_dn)[gw] = make_float2(d0, d1);
    }
}

// ---------------- final combine (also re-zeros g_deg for the next replay) -----
__global__ void k_final(const float* __restrict__ y1, const float* __restrict__ y2,
                        float* __restrict__ out) {
    int n = blockIdx.x*blockDim.x + threadIdx.x;
    int total = gridDim.x*blockDim.x;
    // re-zero degree histogram (dead after k_scan_block; needed zeroed by k_hist
    // on the NEXT graph replay; zero-initialized at module load for the first run)
    for (int i = n; i < NR; i += total) g_deg[i] = 0;
    if (n >= NN) return;
    float m = 0.f;
#pragma unroll
    for (int c = 0; c < 16; c++) m += y2[(size_t)n*16 + c];
    m *= (1.f/16.f);
#pragma unroll
    for (int c = 0; c < 16; c++)
        out[(size_t)n*16 + c] = tanhf(y1[(size_t)n*16 + c] + m);
}

// ---------------- host ----------------
extern "C" void kernel_launch(void* const* d_in, const int* in_sizes, int n_in,
                              void* d_out, int out_size) {
    const float* x  = (const float*)d_in[0];
    const int*   ei = (const int*)d_in[1];
    const int*   et = (const int*)d_in[2];
    const float *rb[3], *rc[3], *rrw[3], *rbias[3], *gw[3], *gas[3], *gad[3], *gb[3];
    for (int k = 0; k < 3; k++) {
        int base = 3 + k*8;
        rb[k]    = (const float*)d_in[base + 0];
        rc[k]    = (const float*)d_in[base + 1];
        rrw[k]   = (const float*)d_in[base + 2];
        rbias[k] = (const float*)d_in[base + 3];
        gw[k]    = (const float*)d_in[base + 4];
        gas[k]   = (const float*)d_in[base + 5];
        gad[k]   = (const float*)d_in[base + 6];
        gb[k]    = (const float*)d_in[base + 7];
    }
    float* out = (float*)d_out;

    float *Z, *h, *A, *Bf, *C, *D;
    cudaGetSymbolAddress((void**)&Z, g_Z);
    cudaGetSymbolAddress((void**)&h, g_h);
    cudaGetSymbolAddress((void**)&A, g_bufA);
    cudaGetSymbolAddress((void**)&Bf, g_bufB);
    cudaGetSymbolAddress((void**)&C, g_bufC);
    cudaGetSymbolAddress((void**)&D, g_bufD);

    dim3 blk(256);
    dim3 grid64((64  + BN - 1)/BN, (NN + BM - 1)/BM);
    dim3 grid16((16  + BN - 1)/BN, (NN + BM - 1)/BM);
    dim3 grid32((32  + BN - 1)/BN, (NN + BM - 1)/BM);
    int aggGrid  = ((2*NN)*32 + 255)/256;
    int wGrid    = (NN*32 + 255)/256;       // 6250
    int gy       = (NN + BM - 1)/BM;        // 391
    int gemm0B   = 2*gy;                    // 782 (NC=128, gx=2)
    int saB      = (NR + 255)/256;          // 1563
    int fillB    = (EE + 255)/256;          // 3125

    // ---- CSR build + GAT-0 projection/attdot (g_deg pre-zeroed by prior k_final) ----
    k_hist<<<(EE + 255)/256, 256>>>(ei, et);
    k_scan_block<<<(NR + 1023)/1024, 1024>>>();
    k_sa_gemm0<<<gemm0B + saB, blk>>>(x, gw[0], h, gemm0B);          // gemm0 || scan_add
    k_fill_attdot<<<fillB + wGrid, blk>>>(ei, et, fillB, h, gas[0], gad[0], 64);

    // ---- layer 0: fused agg (gat h -> Bf, rgcn x -> Z) ----
    k_agg<<<aggGrid, 256>>>(x, rc[0], h, gb[0], Bf, 64, 1);
    // dual: rgcn0 GEMM (Z,rb0 + x,rr0 -> A)  ||  gat1 projection (Bf,gw1 -> h)
    {
        dim3 dgrid(2, gy, 2);
        k_gemm_dual<<<dgrid, blk>>>(
            Z, rb[0], BB*64, x, rrw[0], 64, rbias[0], A, NN, 64, 1, 1,
            Bf, gw[1], 64, nullptr, nullptr, 0, nullptr, h, NN, 128, 0, 2);
    }
    k_attdot<<<wGrid, 256>>>(h, gas[1], gad[1], 64);

    // ---- layer 1 agg + rgcn1 GEMM ----
    k_agg<<<aggGrid, 256>>>(A, rc[1], h, gb[1], D, 64, 1);
    k_gemm<<<grid64, blk>>>(Z, rb[1], BB*64, A, rrw[1], 64, rbias[1], C, NN, 64, 1);

    // ---- swap: rgcn gets GAT branch (D), gat gets RGCN branch (C) ----
    k_gemm<<<grid32, blk>>>(C, gw[2], 64, nullptr, nullptr, 0, nullptr, h, NN, 32, 0);
    k_attdot<<<wGrid, 256>>>(h, gas[2], gad[2], 16);
    k_agg<<<aggGrid, 256>>>(D, rc[2], h, gb[2], Bf, 16, 0);
    k_gemm<<<grid16, blk>>>(Z, rb[2], BB*64, D, rrw[2], 64, rbias[2], A, NN, 16, 0);

    // ---- combine (+ re-zero g_deg for next replay) ----
    k_final<<<(NN + 255)/256, 256>>>(A, Bf, out);
}

// round 15
// speedup vs baseline: 1.0555x; 1.0323x over previous
#include <cuda_runtime.h>
#include <math.h>

#define NN 50000
#define EE 800000
#define RR 8
#define BB 4
#define NHH 2
#define NR (NN*RR)   // 400000
#define NEG 0.2f
#define FULLM 0xFFFFFFFFu

// ---------------- device scratch ----------------
__device__ int g_deg[NR];        // zero at module load; re-zeroed by k_gemm_final each replay
__device__ int g_rowptr[NR+1];
__device__ int g_cur[NR];
__device__ int g_epack[EE];      // src | (rel << 16)
__device__ int g_bsum[512];
__device__ int g_boff[512];
__device__ int g_ctr;

__device__ float g_Z[(size_t)NN*BB*64];   // RGCN basis-folded aggregates [N, 256]
__device__ float g_h[(size_t)NN*NHH*64];  // GAT projected features
__device__ float g_sn[NN*NHH];            // att_src dot (float2-viewable)
__device__ float g_dn[NN*NHH];            // att_dst dot
__device__ float g_bufA[(size_t)NN*64];
__device__ float g_bufB[(size_t)NN*64];
__device__ float g_bufD[(size_t)NN*64];

// ---------------- CSR build ----------------
__global__ void k_hist(const int* __restrict__ ei, const int* __restrict__ et) {
    int e = blockIdx.x*blockDim.x + threadIdx.x;
    if (e >= EE) return;
    int dst = ei[EE + e];
    int r   = et[e];
    atomicAdd(&g_deg[dst*RR + r], 1);
}
// block scan; LAST finishing block also scans per-block sums AND self-resets g_ctr
__global__ void k_scan_block() { // 1024 threads/block
    __shared__ int sh[1024];
    __shared__ bool isLast;
    int i = blockIdx.x*1024 + threadIdx.x;
    int v = (i < NR) ? g_deg[i] : 0;
    sh[threadIdx.x] = v;
    __syncthreads();
    for (int off = 1; off < 1024; off <<= 1) {
        int t = (threadIdx.x >= off) ? sh[threadIdx.x - off] : 0;
        __syncthreads();
        sh[threadIdx.x] += t;
        __syncthreads();
    }
    if (i < NR) g_rowptr[i+1] = sh[threadIdx.x];
    if (threadIdx.x == 1023) g_bsum[blockIdx.x] = sh[1023];
    __threadfence();
    if (threadIdx.x == 0) isLast = (atomicAdd(&g_ctr, 1) == (int)gridDim.x - 1);
    __syncthreads();
    if (!isLast) return;
    int nb = gridDim.x;
    int v2 = (threadIdx.x < 512 && (int)threadIdx.x < nb) ? g_bsum[threadIdx.x] : 0;
    __syncthreads();
    if (threadIdx.x < 512) sh[threadIdx.x] = v2;
    __syncthreads();
    for (int off = 1; off < 512; off <<= 1) {
        int t = (threadIdx.x < 512 && threadIdx.x >= (unsigned)off) ? sh[threadIdx.x - off] : 0;
        __syncthreads();
        if (threadIdx.x < 512) sh[threadIdx.x] += t;
        __syncthreads();
    }
    if ((int)threadIdx.x < nb) g_boff[threadIdx.x] = sh[threadIdx.x] - v2; // exclusive
    if (threadIdx.x == 0) g_ctr = 0;   // self-reset for next graph replay
}

__device__ __forceinline__ float leaky(float v) { return v > 0.f ? v : NEG*v; }

// ---------------- RGCN per-node body (R9-proven: float2, MLP-batched) ----------
__device__ __forceinline__ void rgcn_node(int n, int lane, const float* __restrict__ X,
                                          const float* __restrict__ rc) {
    int rp = 0;
    if (lane <= 8) rp = g_rowptr[n*RR + lane];
    int s   = __shfl_sync(FULLM, rp, 0);
    int e8  = __shfl_sync(FULLM, rp, 8);
    int deg = e8 - s;
    int nxt = __shfl_down_sync(FULLM, rp, 1);
    int cseg = nxt - rp;
    float invr = (lane < 8 && cseg > 0) ? 1.0f/(float)cseg : 0.f;
    float rcw = rc[lane] * __shfl_sync(FULLM, invr, lane >> 2);
    float2 z0 = {0.f,0.f}, z1 = {0.f,0.f}, z2 = {0.f,0.f}, z3 = {0.f,0.f};
    const float2* Xb = (const float2*)X;
    for (int base = 0; base < deg; base += 32) {
        int cnt = min(32, deg - base);
        int pk = (lane < cnt) ? g_epack[s + base + lane] : 0;
        int j = 0;
        for (; j + 4 <= cnt; j += 4) {
            int p0 = __shfl_sync(FULLM, pk, j);
            int p1 = __shfl_sync(FULLM, pk, j+1);
            int p2 = __shfl_sync(FULLM, pk, j+2);
            int p3 = __shfl_sync(FULLM, pk, j+3);
            float2 v0 = Xb[(size_t)(p0 & 0xFFFF)*32 + lane];
            float2 v1 = Xb[(size_t)(p1 & 0xFFFF)*32 + lane];
            float2 v2 = Xb[(size_t)(p2 & 0xFFFF)*32 + lane];
            float2 v3 = Xb[(size_t)(p3 & 0xFFFF)*32 + lane];
            int r0 = (p0 >> 16) << 2, r1 = (p1 >> 16) << 2;
            int r2 = (p2 >> 16) << 2, r3 = (p3 >> 16) << 2;
            float w;
            w = __shfl_sync(FULLM, rcw, r0+0); z0.x += w*v0.x; z0.y += w*v0.y;
            w = __shfl_sync(FULLM, rcw, r0+1); z1.x += w*v0.x; z1.y += w*v0.y;
            w = __shfl_sync(FULLM, rcw, r0+2); z2.x += w*v0.x; z2.y += w*v0.y;
            w = __shfl_sync(FULLM, rcw, r0+3); z3.x += w*v0.x; z3.y += w*v0.y;
            w = __shfl_sync(FULLM, rcw, r1+0); z0.x += w*v1.x; z0.y += w*v1.y;
            w = __shfl_sync(FULLM, rcw, r1+1); z1.x += w*v1.x; z1.y += w*v1.y;
            w = __shfl_sync(FULLM, rcw, r1+2); z2.x += w*v1.x; z2.y += w*v1.y;
            w = __shfl_sync(FULLM, rcw, r1+3); z3.x += w*v1.x; z3.y += w*v1.y;
            w = __shfl_sync(FULLM, rcw, r2+0); z0.x += w*v2.x; z0.y += w*v2.y;
            w = __shfl_sync(FULLM, rcw, r2+1); z1.x += w*v2.x; z1.y += w*v2.y;
            w = __shfl_sync(FULLM, rcw, r2+2); z2.x += w*v2.x; z2.y += w*v2.y;
            w = __shfl_sync(FULLM, rcw, r2+3); z3.x += w*v2.x; z3.y += w*v2.y;
            w = __shfl_sync(FULLM, rcw, r3+0); z0.x += w*v3.x; z0.y += w*v3.y;
            w = __shfl_sync(FULLM, rcw, r3+1); z1.x += w*v3.x; z1.y += w*v3.y;
            w = __shfl_sync(FULLM, rcw, r3+2); z2.x += w*v3.x; z2.y += w*v3.y;
            w = __shfl_sync(FULLM, rcw, r3+3); z3.x += w*v3.x; z3.y += w*v3.y;
        }
        for (; j < cnt; j++) {
            int p0 = __shfl_sync(FULLM, pk, j);
            float2 v0 = Xb[(size_t)(p0 & 0xFFFF)*32 + lane];
            int r0 = (p0 >> 16) << 2;
            float w;
            w = __shfl_sync(FULLM, rcw, r0+0); z0.x += w*v0.x; z0.y += w*v0.y;
            w = __shfl_sync(FULLM, rcw, r0+1); z1.x += w*v0.x; z1.y += w*v0.y;
            w = __shfl_sync(FULLM, rcw, r0+2); z2.x += w*v0.x; z2.y += w*v0.y;
            w = __shfl_sync(FULLM, rcw, r0+3); z3.x += w*v0.x; z3.y += w*v0.y;
        }
    }
    float2* Zb = (float2*)g_Z;
    size_t o = (size_t)n*128;
    Zb[o + lane]      = z0;
    Zb[o + 32 + lane] = z1;
    Zb[o + 64 + lane] = z2;
    Zb[o + 96 + lane] = z3;
}

// ---------------- GAT per-node body (R5-proven: single-pass, no max shift) -----
__device__ __forceinline__ void gat_node(int n, int lane, const float* __restrict__ h,
                                         const float* __restrict__ bias,
                                         float* __restrict__ Y, int C, int relu) {
    int s = g_rowptr[n*RR];
    int t = g_rowptr[n*RR + RR];
    float2 dn  = ((const float2*)g_dn)[n];
    float2 snn = ((const float2*)g_sn)[n];
    bool act = (2*lane < C);
    int C2 = C >> 1;
    const float2* hb = (const float2*)h;   // row stride = C float2
    float den0l = 0.f, den1l = 0.f;
    float2 acc0, acc1;
    {   // self-loop
        float e0 = __expf(leaky(snn.x + dn.x));
        float e1 = __expf(leaky(snn.y + dn.y));
        if (lane == 0) { den0l = e0; den1l = e1; }
        size_t ro = (size_t)n*C;
        float2 v0 = act ? hb[ro + lane]      : make_float2(0.f,0.f);
        float2 v1 = act ? hb[ro + C2 + lane] : make_float2(0.f,0.f);
        acc0 = make_float2(e0*v0.x, e0*v0.y);
        acc1 = make_float2(e1*v1.x, e1*v1.y);
    }
    for (int base = s; base < t; base += 32) {
        int cnt = min(32, t - base);
        int pk = 0; float e0l = 0.f, e1l = 0.f;
        if (lane < cnt) {
            pk = g_epack[base + lane];
            float2 sv = ((const float2*)g_sn)[pk & 0xFFFF];
            e0l = __expf(leaky(sv.x + dn.x));
            e1l = __expf(leaky(sv.y + dn.y));
        }
        den0l += e0l; den1l += e1l;
        int j = 0;
        for (; j + 4 <= cnt; j += 4) {
            int p0 = __shfl_sync(FULLM, pk, j);
            int p1 = __shfl_sync(FULLM, pk, j+1);
            int p2 = __shfl_sync(FULLM, pk, j+2);
            int p3 = __shfl_sync(FULLM, pk, j+3);
            float f00 = __shfl_sync(FULLM, e0l, j),   f10 = __shfl_sync(FULLM, e1l, j);
            float f01 = __shfl_sync(FULLM, e0l, j+1), f11 = __shfl_sync(FULLM, e1l, j+1);
            float f02 = __shfl_sync(FULLM, e0l, j+2), f12 = __shfl_sync(FULLM, e1l, j+2);
            float f03 = __shfl_sync(FULLM, e0l, j+3), f13 = __shfl_sync(FULLM, e1l, j+3);
            size_t r0 = (size_t)(p0 & 0xFFFF)*C, r1 = (size_t)(p1 & 0xFFFF)*C;
            size_t r2 = (size_t)(p2 & 0xFFFF)*C, r3 = (size_t)(p3 & 0xFFFF)*C;
            float2 zr = make_float2(0.f,0.f);
            float2 a0 = act ? hb[r0 + lane] : zr, b0 = act ? hb[r0 + C2 + lane] : zr;
            float2 a1 = act ? hb[r1 + lane] : zr, b1 = act ? hb[r1 + C2 + lane] : zr;
            float2 a2 = act ? hb[r2 + lane] : zr, b2 = act ? hb[r2 + C2 + lane] : zr;
            float2 a3 = act ? hb[r3 + lane] : zr, b3 = act ? hb[r3 + C2 + lane] : zr;
            acc0.x += f00*a0.x; acc0.y += f00*a0.y; acc1.x += f10*b0.x; acc1.y += f10*b0.y;
            acc0.x += f01*a1.x; acc0.y += f01*a1.y; acc1.x += f11*b1.x; acc1.y += f11*b1.y;
            acc0.x += f02*a2.x; acc0.y += f02*a2.y; acc1.x += f12*b2.x; acc1.y += f12*b2.y;
            acc0.x += f03*a3.x; acc0.y += f03*a3.y; acc1.x += f13*b3.x; acc1.y += f13*b3.y;
        }
        for (; j < cnt; j++) {
            int p0 = __shfl_sync(FULLM, pk, j);
            float f0 = __shfl_sync(FULLM, e0l, j), f1 = __shfl_sync(FULLM, e1l, j);
            size_t r0 = (size_t)(p0 & 0xFFFF)*C;
            float2 zr = make_float2(0.f,0.f);
            float2 a0 = act ? hb[r0 + lane] : zr, b0 = act ? hb[r0 + C2 + lane] : zr;
            acc0.x += f0*a0.x; acc0.y += f0*a0.y;
            acc1.x += f1*b0.x; acc1.y += f1*b0.y;
        }
    }
#pragma unroll
    for (int off = 16; off; off >>= 1) {
        den0l += __shfl_xor_sync(FULLM, den0l, off);
        den1l += __shfl_xor_sync(FULLM, den1l, off);
    }
    if (act) {
        float i0 = 1.f/den0l, i1 = 1.f/den1l;
        int c = 2*lane;
        float vx = 0.5f*(acc0.x*i0 + acc1.x*i1) + bias[c];
        float vy = 0.5f*(acc0.y*i0 + acc1.y*i1) + bias[c + 1];
        if (relu) { vx = fmaxf(vx, 0.f); vy = fmaxf(vy, 0.f); }
        Y[(size_t)n*C + c]     = vx;
        Y[(size_t)n*C + c + 1] = vy;
    }
}

// ---------------- fused per-layer aggregation: GAT warps first, then RGCN -----
__global__ void k_agg(const float* __restrict__ XR, const float* __restrict__ rc,
                      const float* __restrict__ h, const float* __restrict__ gb,
                      float* __restrict__ Yg, int C, int relu) {
    int gw = (blockIdx.x*blockDim.x + threadIdx.x) >> 5;
    int lane = threadIdx.x & 31;
    if (gw < NN)          gat_node(gw, lane, h, gb, Yg, C, relu);
    else if (gw < 2*NN)   rgcn_node(gw - NN, lane, XR, rc);
}

// ---------------- TF32 tensor-core GEMM ----------------
__device__ __forceinline__ unsigned f2tf(float x) {
    unsigned r;
    asm("cvt.rna.tf32.f32 %0, %1;" : "=r"(r) : "f"(x));
    return r;
}
__device__ __forceinline__ void mma_tf32(float d[4], const unsigned a[4],
                                         const unsigned b[2], const float c[4]) {
    asm volatile(
        "mma.sync.aligned.m16n8k8.row.col.f32.tf32.tf32.f32 "
        "{%0,%1,%2,%3}, {%4,%5,%6,%7}, {%8,%9}, {%10,%11,%12,%13};\n"
        : "=f"(d[0]), "=f"(d[1]), "=f"(d[2]), "=f"(d[3])
        : "r"(a[0]), "r"(a[1]), "r"(a[2]), "r"(a[3]),
          "r"(b[0]), "r"(b[1]),
          "f"(c[0]), "f"(c[1]), "f"(c[2]), "f"(c[3]));
}

#define BM 128
#define BN 64
#define BK 32
#define KSTR (BK + 4)

__device__ __forceinline__ void ld_tileA(const float* __restrict__ A, int K, int M,
                                         int m0, int k0, int tid, float4 pa[4]) {
#pragma unroll
    for (int it = 0; it < 4; it++) {
        int idx = tid + it*256;
        int m = idx >> 3, kq = (idx & 7) << 2;
        int gm = m0 + m;
        pa[it] = (gm < M) ? *reinterpret_cast<const float4*>(&A[(size_t)gm*K + k0 + kq])
                          : make_float4(0.f,0.f,0.f,0.f);
    }
}
__device__ __forceinline__ void ld_tileB(const float* __restrict__ Bm, int NC,
                                         int n0, int k0, int tid, float pb[8]) {
#pragma unroll
    for (int it = 0; it < 8; it++) {
        int idx = tid + it*256;
        int k = idx >> 6, nn = idx & 63;
        int gn = n0 + nn;
        pb[it] = (gn < NC) ? Bm[(size_t)(k0 + k)*NC + gn] : 0.f;
    }
}

// mainloop only; caller owns shared memory and epilogue
__device__ __forceinline__ void gemm_core(
    unsigned (*As)[KSTR], unsigned (*Bs)[KSTR],
    const float* __restrict__ A1, const float* __restrict__ B1, int K1,
    const float* __restrict__ A2, const float* __restrict__ B2, int K2,
    int M, int NC, int m0, int n0, int tid,
    int warp_m, int warp_n, int g, int t,
    float acc[2][4][4])
{
    float4 pa[4];
    float  pb[8];
    for (int pass = 0; pass < 2; pass++) {
        const float* A  = pass ? A2 : A1;
        const float* Bm = pass ? B2 : B1;
        int K = pass ? K2 : K1;
        if (K == 0 || A == nullptr) continue;
        ld_tileA(A, K, M, m0, 0, tid, pa);
        ld_tileB(Bm, NC, n0, 0, tid, pb);
        for (int k0 = 0; k0 < K; k0 += BK) {
#pragma unroll
            for (int it = 0; it < 4; it++) {
                int idx = tid + it*256;
                int m = idx >> 3, kq = (idx & 7) << 2;
                unsigned* p = &As[m][kq];
                p[0] = f2tf(pa[it].x); p[1] = f2tf(pa[it].y);
                p[2] = f2tf(pa[it].z); p[3] = f2tf(pa[it].w);
            }
#pragma unroll
            for (int it = 0; it < 8; it++) {
                int idx = tid + it*256;
                int k = idx >> 6, nn = idx & 63;
                Bs[nn][k] = f2tf(pb[it]);
            }
            __syncthreads();
            if (k0 + BK < K) {
                ld_tileA(A, K, M, m0, k0 + BK, tid, pa);
                ld_tileB(Bm, NC, n0, k0 + BK, tid, pb);
            }
#pragma unroll
            for (int kk = 0; kk < BK; kk += 8) {
                unsigned afr[2][4];
#pragma unroll
                for (int am = 0; am < 2; am++) {
                    int row = warp_m + am*16 + g;
                    afr[am][0] = As[row][kk + t];
                    afr[am][1] = As[row + 8][kk + t];
                    afr[am][2] = As[row][kk + t + 4];
                    afr[am][3] = As[row + 8][kk + t + 4];
                }
                unsigned bfr[4][2];
#pragma unroll
                for (int an = 0; an < 4; an++) {
                    int col = warp_n + an*8 + g;
                    bfr[an][0] = Bs[col][kk + t];
                    bfr[an][1] = Bs[col][kk + t + 4];
                }
#pragma unroll
                for (int am = 0; am < 2; am++)
#pragma unroll
                    for (int an = 0; an < 4; an++)
                        mma_tf32(acc[am][an], afr[am], bfr[an], acc[am][an]);
            }
            __syncthreads();
        }
    }
}

__device__ __forceinline__ void gemm_body(
    const float* __restrict__ A1, const float* __restrict__ B1, int K1,
    const float* __restrict__ A2, const float* __restrict__ B2, int K2,
    const float* __restrict__ bias, float* __restrict__ Y,
    int M, int NC, int relu, int bx, int by)
{
    __shared__ __align__(16) unsigned As[BM][KSTR];
    __shared__ __align__(16) unsigned Bs[BN][KSTR];
    int tid = threadIdx.x;
    int wid = tid >> 5, lane = tid & 31;
    int g = lane >> 2, t = lane & 3;
    int warp_m = (wid >> 1) * 32;
    int warp_n = (wid & 1) * 32;
    int m0 = by * BM, n0 = bx * BN;
    float acc[2][4][4] = {};
    gemm_core(As, Bs, A1, B1, K1, A2, B2, K2, M, NC, m0, n0, tid, warp_m, warp_n, g, t, acc);
#pragma unroll
    for (int am = 0; am < 2; am++) {
#pragma unroll
        for (int an = 0; an < 4; an++) {
#pragma unroll
            for (int i = 0; i < 4; i++) {
                int row = warp_m + am*16 + g + (i >> 1)*8;
                int col = warp_n + an*8 + 2*t + (i & 1);
                int gm = m0 + row, gn = n0 + col;
                if (gm < M && gn < NC) {
                    float v = acc[am][an][i] + (bias ? bias[gn] : 0.f);
                    if (relu) v = fmaxf(v, 0.f);
                    Y[(size_t)gm*NC + gn] = v;
                }
            }
        }
    }
}

// two independent GEMMs in one launch; blockIdx.z selects the problem.
__global__ void k_gemm_dual(
    const float* __restrict__ pA1, const float* __restrict__ pB1, int pK1,
    const float* __restrict__ pA2, const float* __restrict__ pB2, int pK2,
    const float* __restrict__ pbias, float* __restrict__ pY,
    int pM, int pNC, int prelu, int pGX,
    const float* __restrict__ qA1, const float* __restrict__ qB1, int qK1,
    const float* __restrict__ qA2, const float* __restrict__ qB2, int qK2,
    const float* __restrict__ qbias, float* __restrict__ qY,
    int qM, int qNC, int qrelu, int qGX)
{
    if (blockIdx.z == 0) {
        if ((int)blockIdx.x >= pGX) return;
        gemm_body(pA1, pB1, pK1, pA2, pB2, pK2, pbias, pY, pM, pNC, prelu,
                  blockIdx.x, blockIdx.y);
    } else {
        if ((int)blockIdx.x >= qGX) return;
        gemm_body(qA1, qB1, qK1, qA2, qB2, qK2, qbias, qY, qM, qNC, qrelu,
                  blockIdx.x, blockIdx.y);
    }
}

// ---- chained: C = relu(Z@rb1 + A@rr1 + bias) kept in smem; h = C @ gw2 -------
// NC=64 == BN so each block owns full rows of C; C never hits global memory.
__global__ void __launch_bounds__(256) k_gemm_chain(
    const float* __restrict__ Z, const float* __restrict__ rb1,
    const float* __restrict__ A, const float* __restrict__ rr1,
    const float* __restrict__ rbias1, const float* __restrict__ gw2,
    float* __restrict__ h)
{
    __shared__ __align__(16) char sbuf[128*68*4 + 32*68*4];   // 43520 B
    unsigned (*As)[KSTR] = reinterpret_cast<unsigned(*)[KSTR]>(sbuf);
    unsigned (*Bs)[KSTR] = reinterpret_cast<unsigned(*)[KSTR]>(sbuf + BM*KSTR*4);
    int tid = threadIdx.x;
    int wid = tid >> 5, lane = tid & 31;
    int g = lane >> 2, t = lane & 3;
    int warp_m = (wid >> 1) * 32;
    int warp_n = (wid & 1) * 32;
    int m0 = blockIdx.x * BM;

    float acc[2][4][4] = {};
    gemm_core(As, Bs, Z, rb1, BB*64, A, rr1, 64, NN, 64, m0, 0, tid, warp_m, warp_n, g, t, acc);
    // phase 2 smem views (overlap As/Bs; all reads drained by last sync in core)
    unsigned (*Cs)[68]  = reinterpret_cast<unsigned(*)[68]>(sbuf);
    unsigned (*Bs2)[68] = reinterpret_cast<unsigned(*)[68]>(sbuf + 128*68*4);
#pragma unroll
    for (int am = 0; am < 2; am++)
#pragma unroll
        for (int an = 0; an < 4; an++)
#pragma unroll
            for (int i = 0; i < 4; i++) {
                int row = warp_m + am*16 + g + (i >> 1)*8;
                int col = warp_n + an*8 + 2*t + (i & 1);
                float v = fmaxf(acc[am][an][i] + rbias1[col], 0.f);
                Cs[row][col] = f2tf(v);
            }
    for (int idx = tid; idx < 64*32; idx += 256) {
        int k = idx >> 5, nn = idx & 31;
        Bs2[nn][k] = f2tf(gw2[idx]);
    }
    __syncthreads();
    float acc2[2][4][4] = {};
#pragma unroll
    for (int kk = 0; kk < 64; kk += 8) {
        unsigned afr[2][4];
#pragma unroll
        for (int am = 0; am < 2; am++) {
            int row = warp_m + am*16 + g;
            afr[am][0] = Cs[row][kk + t];
            afr[am][1] = Cs[row + 8][kk + t];
            afr[am][2] = Cs[row][kk + t + 4];
            afr[am][3] = Cs[row + 8][kk + t + 4];
        }
        unsigned bfr[4][2];
#pragma unroll
        for (int an = 0; an < 4; an++) {
            int col = warp_n + an*8 + g;
            int cc = (col < 32) ? col : 0;
            bfr[an][0] = Bs2[cc][kk + t];
            bfr[an][1] = Bs2[cc][kk + t + 4];
        }
#pragma unroll
        for (int am = 0; am < 2; am++)
#pragma unroll
            for (int an = 0; an < 4; an++)
                mma_tf32(acc2[am][an], afr[am], bfr[an], acc2[am][an]);
    }
#pragma unroll
    for (int am = 0; am < 2; am++)
#pragma unroll
        for (int an = 0; an < 4; an++)
#pragma unroll
            for (int i = 0; i < 4; i++) {
                int row = warp_m + am*16 + g + (i >> 1)*8;
                int gn = warp_n + an*8 + 2*t + (i & 1);
                int gm = m0 + row;
                if (gm < NN && gn < 32)
                    h[(size_t)gm*32 + gn] = acc2[am][an][i];
            }
}

// ---- final rgcn GEMM (NC=16) fused with tanh(A + mean(Bf)) + g_deg re-zero ---
__global__ void __launch_bounds__(256) k_gemm_final(
    const float* __restrict__ Z, const float* __restrict__ rb2,
    const float* __restrict__ D, const float* __restrict__ rr2,
    const float* __restrict__ rbias2, const float* __restrict__ Bf,
    float* __restrict__ out)
{
    // re-zero degree histogram for the next graph replay
    for (int i = blockIdx.x*blockDim.x + threadIdx.x; i < NR; i += gridDim.x*blockDim.x)
        g_deg[i] = 0;
    __shared__ __align__(16) unsigned As[BM][KSTR];
    __shared__ __align__(16) unsigned Bs[BN][KSTR];
    int tid = threadIdx.x;
    int wid = tid >> 5, lane = tid & 31;
    int g = lane >> 2, t = lane & 3;
    int warp_m = (wid >> 1) * 32;
    int warp_n = (wid & 1) * 32;
    int m0 = blockIdx.x * BM;

    float acc[2][4][4] = {};
    gemm_core(As, Bs, Z, rb2, BB*64, D, rr2, 64, NN, 16, m0, 0, tid, warp_m, warp_n, g, t, acc);
    // Bf row means (t==0 lane loads, broadcast within the g-group)
    float rmean[2][2];
#pragma unroll
    for (int am = 0; am < 2; am++)
#pragma unroll
        for (int ih = 0; ih < 2; ih++) {
            int gm = m0 + warp_m + am*16 + g + ih*8;
            float m = 0.f;
            if (t == 0 && gm < NN) {
                const float4* bp = (const float4*)(Bf + (size_t)gm*16);
                float4 b0 = bp[0], b1 = bp[1], b2 = bp[2], b3 = bp[3];
                m = ((b0.x+b0.y+b0.z+b0.w) + (b1.x+b1.y+b1.z+b1.w)
                   + (b2.x+b2.y+b2.z+b2.w) + (b3.x+b3.y+b3.z+b3.w)) * (1.f/16.f);
            }
            m = __shfl_sync(FULLM, m, lane & ~3);
            rmean[am][ih] = m;
        }
#pragma unroll
    for (int am = 0; am < 2; am++)
#pragma unroll
        for (int an = 0; an < 4; an++)
#pragma unroll
            for (int i = 0; i < 4; i++) {
                int row = warp_m + am*16 + g + (i >> 1)*8;
                int gn = warp_n + an*8 + 2*t + (i & 1);
                int gm = m0 + row;
                if (gm < NN && gn < 16) {
                    float v = acc[am][an][i] + rbias2[gn];
                    out[(size_t)gm*16 + gn] = tanhf(v + rmean[am][i >> 1]);
                }
            }
}

// ---- fused: gemm0 (x@gw0 -> h, NC=128) blocks, then scan_add blocks ----------
__global__ void k_sa_gemm0(const float* __restrict__ x, const float* __restrict__ gw0,
                           float* __restrict__ h, int gemmBlocks) {
    int bid = blockIdx.x;
    if (bid < gemmBlocks) {
        gemm_body(x, gw0, 64, nullptr, nullptr, 0, nullptr, h, NN, 128, 0,
                  bid & 1, bid >> 1);
    } else {
        int i = (bid - gemmBlocks)*blockDim.x + threadIdx.x;
        if (i < NR) {
            int v = g_rowptr[i+1] + g_boff[i >> 10];
            g_rowptr[i+1] = v;
            if (i + 1 < NR) g_cur[i+1] = v;
        }
        if (i == 0) { g_rowptr[0] = 0; g_cur[0] = 0; }
    }
}

// ---- fused: fill blocks, then attdot0 blocks ---------------------------------
__global__ void k_fill_attdot(const int* __restrict__ ei, const int* __restrict__ et,
                              int fillBlocks, const float* __restrict__ h,
                              const float* __restrict__ gas, const float* __restrict__ gad,
                              int C) {
    int bid = blockIdx.x;
    if (bid < fillBlocks) {
        int e = bid*blockDim.x + threadIdx.x;
        if (e >= EE) return;
        int src = ei[e];
        int dst = ei[EE + e];
        int r   = et[e];
        int p = atomicAdd(&g_cur[dst*RR + r], 1);
        g_epack[p] = src | (r << 16);
    } else {
        int gw = ((bid - fillBlocks)*blockDim.x + threadIdx.x) >> 5;
        int lane = threadIdx.x & 31;
        if (gw >= NN) return;
        int C2 = C >> 1;
        const float2* hb = (const float2*)h;
        const float2* gs = (const float2*)gas;
        const float2* gd = (const float2*)gad;
        size_t ro = (size_t)gw*C;
        float s0 = 0.f, d0 = 0.f, s1 = 0.f, d1 = 0.f;
        for (int i = lane; i < C2; i += 32) {
            float2 v0 = hb[ro + i], v1 = hb[ro + C2 + i];
            float2 a0 = gs[i], a1 = gs[C2 + i];
            float2 b0 = gd[i], b1 = gd[C2 + i];
            s0 += v0.x*a0.x + v0.y*a0.y;  d0 += v0.x*b0.x + v0.y*b0.y;
            s1 += v1.x*a1.x + v1.y*a1.y;  d1 += v1.x*b1.x + v1.y*b1.y;
        }
#pragma unroll
        for (int off = 16; off; off >>= 1) {
            s0 += __shfl_xor_sync(FULLM, s0, off);
            d0 += __shfl_xor_sync(FULLM, d0, off);
            s1 += __shfl_xor_sync(FULLM, s1, off);
            d1 += __shfl_xor_sync(FULLM, d1, off);
        }
        if (lane == 0) {
            ((float2*)g_sn)[gw] = make_float2(s0, s1);
            ((float2*)g_dn)[gw] = make_float2(d0, d1);
        }
    }
}

// ---------------- attention dots: warp per node, coalesced ----------------
__global__ void k_attdot(const float* __restrict__ h, const float* __restrict__ gas,
                         const float* __restrict__ gad, int C) {
    int gw = (blockIdx.x*blockDim.x + threadIdx.x) >> 5;
    int lane = threadIdx.x & 31;
    if (gw >= NN) return;
    int C2 = C >> 1;
    const float2* hb = (const float2*)h;
    const float2* gs = (const float2*)gas;
    const float2* gd = (const float2*)gad;
    size_t ro = (size_t)gw*C;
    float s0 = 0.f, d0 = 0.f, s1 = 0.f, d1 = 0.f;
    for (int i = lane; i < C2; i += 32) {
        float2 v0 = hb[ro + i], v1 = hb[ro + C2 + i];
        float2 a0 = gs[i], a1 = gs[C2 + i];
        float2 b0 = gd[i], b1 = gd[C2 + i];
        s0 += v0.x*a0.x + v0.y*a0.y;  d0 += v0.x*b0.x + v0.y*b0.y;
        s1 += v1.x*a1.x + v1.y*a1.y;  d1 += v1.x*b1.x + v1.y*b1.y;
    }
#pragma unroll
    for (int off = 16; off; off >>= 1) {
        s0 += __shfl_xor_sync(FULLM, s0, off);
        d0 += __shfl_xor_sync(FULLM, d0, off);
        s1 += __shfl_xor_sync(FULLM, s1, off);
        d1 += __shfl_xor_sync(FULLM, d1, off);
    }
    if (lane == 0) {
        ((float2*)g_sn)[gw] = make_float2(s0, s1);
        ((float2*)g_dn)[gw] = make_float2(d0, d1);
    }
}

// ---------------- host ----------------
extern "C" void kernel_launch(void* const* d_in, const int* in_sizes, int n_in,
                              void* d_out, int out_size) {
    const float* x  = (const float*)d_in[0];
    const int*   ei = (const int*)d_in[1];
    const int*   et = (const int*)d_in[2];
    const float *rb[3], *rc[3], *rrw[3], *rbias[3], *gw[3], *gas[3], *gad[3], *gb[3];
    for (int k = 0; k < 3; k++) {
        int base = 3 + k*8;
        rb[k]    = (const float*)d_in[base + 0];
        rc[k]    = (const float*)d_in[base + 1];
        rrw[k]   = (const float*)d_in[base + 2];
        rbias[k] = (const float*)d_in[base + 3];
        gw[k]    = (const float*)d_in[base + 4];
        gas[k]   = (const float*)d_in[base + 5];
        gad[k]   = (const float*)d_in[base + 6];
        gb[k]    = (const float*)d_in[base + 7];
    }
    float* out = (float*)d_out;

    float *Z, *h, *A, *Bf, *D;
    cudaGetSymbolAddress((void**)&Z, g_Z);
    cudaGetSymbolAddress((void**)&h, g_h);
    cudaGetSymbolAddress((void**)&A, g_bufA);
    cudaGetSymbolAddress((void**)&Bf, g_bufB);
    cudaGetSymbolAddress((void**)&D, g_bufD);

    dim3 blk(256);
    int aggGrid  = ((2*NN)*32 + 255)/256;
    int wGrid    = (NN*32 + 255)/256;       // 6250
    int gy       = (NN + BM - 1)/BM;        // 391
    int gemm0B   = 2*gy;                    // 782 (NC=128, gx=2)
    int saB      = (NR + 255)/256;          // 1563
    int fillB    = (EE + 255)/256;          // 3125

    // ---- CSR build + GAT-0 projection/attdot (g_deg pre-zeroed by prior k_gemm_final) ----
    k_hist<<<(EE + 255)/256, 256>>>(ei, et);
    k_scan_block<<<(NR + 1023)/1024, 1024>>>();
    k_sa_gemm0<<<gemm0B + saB, blk>>>(x, gw[0], h, gemm0B);          // gemm0 || scan_add
    k_fill_attdot<<<fillB + wGrid, blk>>>(ei, et, fillB, h, gas[0], gad[0], 64);

    // ---- layer 0: fused agg (gat h -> Bf, rgcn x -> Z) ----
    k_agg<<<aggGrid, 256>>>(x, rc[0], h, gb[0], Bf, 64, 1);
    // dual: rgcn0 GEMM (Z,rb0 + x,rr0 -> A)  ||  gat1 projection (Bf,gw1 -> h)
    {
        dim3 dgrid(2, gy, 2);
        k_gemm_dual<<<dgrid, blk>>>(
            Z, rb[0], BB*64, x, rrw[0], 64, rbias[0], A, NN, 64, 1, 1,
            Bf, gw[1], 64, nullptr, nullptr, 0, nullptr, h, NN, 128, 0, 2);
    }
    k_attdot<<<wGrid, 256>>>(h, gas[1], gad[1], 64);

    // ---- layer 1 agg, then chained rgcn1 GEMM + gat2 projection (C stays in smem) ----
    k_agg<<<aggGrid, 256>>>(A, rc[1], h, gb[1], D, 64, 1);
    k_gemm_chain<<<gy, blk>>>(Z, rb[1], A, rrw[1], rbias[1], gw[2], h);
    k_attdot<<<wGrid, 256>>>(h, gas[2], gad[2], 16);

    // ---- layer 2 agg (gat D-branch -> Bf, rgcn D -> Z), then fused rgcn2+final ----
    k_agg<<<aggGrid, 256>>>(D, rc[2], h, gb[2], Bf, 16, 0);
    k_gemm_final<<<gy, blk>>>(Z, rb[2], D, rrw[2], rbias[2], Bf, out);
}

// round 16
// speedup vs baseline: 1.1011x; 1.0432x over previous
#include <cuda_runtime.h>
#include <math.h>

#define NN 50000
#define EE 800000
#define RR 8
#define BB 4
#define NHH 2
#define NR (NN*RR)   // 400000
#define NEG 0.2f
#define FULLM 0xFFFFFFFFu

// ---------------- device scratch ----------------
__device__ int g_deg[NR];        // zero at module load; re-zeroed by k_gemm_final each replay
__device__ int g_rowptr[NR+1];
__device__ int g_cur[NR];
__device__ int g_epack[EE];      // src | (rel << 16)
__device__ int g_bsum[512];
__device__ int g_boff[512];
__device__ int g_ctr;

__device__ float g_Z[(size_t)NN*BB*64];   // RGCN basis-folded aggregates [N, 256]
__device__ float g_h[(size_t)NN*NHH*64];  // GAT projected features
__device__ float g_sn[NN*NHH];            // att_src dot (float2-viewable)
__device__ float g_dn[NN*NHH];            // att_dst dot
__device__ float g_bufA[(size_t)NN*64];
__device__ float g_bufB[(size_t)NN*64];
__device__ float g_bufD[(size_t)NN*64];

// ---------------- CSR build ----------------
__global__ void k_hist(const int* __restrict__ ei, const int* __restrict__ et) {
    int e = blockIdx.x*blockDim.x + threadIdx.x;
    if (e >= EE) return;
    int dst = ei[EE + e];
    int r   = et[e];
    atomicAdd(&g_deg[dst*RR + r], 1);
}
// block scan; LAST finishing block also scans per-block sums AND self-resets g_ctr
__global__ void k_scan_block() { // 1024 threads/block
    __shared__ int sh[1024];
    __shared__ bool isLast;
    int i = blockIdx.x*1024 + threadIdx.x;
    int v = (i < NR) ? g_deg[i] : 0;
    sh[threadIdx.x] = v;
    __syncthreads();
    for (int off = 1; off < 1024; off <<= 1) {
        int t = (threadIdx.x >= off) ? sh[threadIdx.x - off] : 0;
        __syncthreads();
        sh[threadIdx.x] += t;
        __syncthreads();
    }
    if (i < NR) g_rowptr[i+1] = sh[threadIdx.x];
    if (threadIdx.x == 1023) g_bsum[blockIdx.x] = sh[1023];
    __threadfence();
    if (threadIdx.x == 0) isLast = (atomicAdd(&g_ctr, 1) == (int)gridDim.x - 1);
    __syncthreads();
    if (!isLast) return;
    int nb = gridDim.x;
    int v2 = (threadIdx.x < 512 && (int)threadIdx.x < nb) ? g_bsum[threadIdx.x] : 0;
    __syncthreads();
    if (threadIdx.x < 512) sh[threadIdx.x] = v2;
    __syncthreads();
    for (int off = 1; off < 512; off <<= 1) {
        int t = (threadIdx.x < 512 && threadIdx.x >= (unsigned)off) ? sh[threadIdx.x - off] : 0;
        __syncthreads();
        if (threadIdx.x < 512) sh[threadIdx.x] += t;
        __syncthreads();
    }
    if ((int)threadIdx.x < nb) g_boff[threadIdx.x] = sh[threadIdx.x] - v2; // exclusive
    if (threadIdx.x == 0) g_ctr = 0;   // self-reset for next graph replay
}
__global__ void k_fill(const int* __restrict__ ei, const int* __restrict__ et) {
    int e = blockIdx.x*blockDim.x + threadIdx.x;
    if (e >= EE) return;
    int src = ei[e];
    int dst = ei[EE + e];
    int r   = et[e];
    int p = atomicAdd(&g_cur[dst*RR + r], 1);
    g_epack[p] = src | (r << 16);
}

__device__ __forceinline__ float leaky(float v) { return v > 0.f ? v : NEG*v; }

// ---------------- RGCN per-node body (R9-proven: float2, MLP-batched) ----------
__device__ __forceinline__ void rgcn_node(int n, int lane, const float* __restrict__ X,
                                          const float* __restrict__ rc) {
    int rp = 0;
    if (lane <= 8) rp = g_rowptr[n*RR + lane];
    int s   = __shfl_sync(FULLM, rp, 0);
    int e8  = __shfl_sync(FULLM, rp, 8);
    int deg = e8 - s;
    int nxt = __shfl_down_sync(FULLM, rp, 1);
    int cseg = nxt - rp;
    float invr = (lane < 8 && cseg > 0) ? 1.0f/(float)cseg : 0.f;
    float rcw = rc[lane] * __shfl_sync(FULLM, invr, lane >> 2);
    float2 z0 = {0.f,0.f}, z1 = {0.f,0.f}, z2 = {0.f,0.f}, z3 = {0.f,0.f};
    const float2* Xb = (const float2*)X;
    for (int base = 0; base < deg; base += 32) {
        int cnt = min(32, deg - base);
        int pk = (lane < cnt) ? g_epack[s + base + lane] : 0;
        int j = 0;
        for (; j + 4 <= cnt; j += 4) {
            int p0 = __shfl_sync(FULLM, pk, j);
            int p1 = __shfl_sync(FULLM, pk, j+1);
            int p2 = __shfl_sync(FULLM, pk, j+2);
            int p3 = __shfl_sync(FULLM, pk, j+3);
            float2 v0 = Xb[(size_t)(p0 & 0xFFFF)*32 + lane];
            float2 v1 = Xb[(size_t)(p1 & 0xFFFF)*32 + lane];
            float2 v2 = Xb[(size_t)(p2 & 0xFFFF)*32 + lane];
            float2 v3 = Xb[(size_t)(p3 & 0xFFFF)*32 + lane];
            int r0 = (p0 >> 16) << 2, r1 = (p1 >> 16) << 2;
            int r2 = (p2 >> 16) << 2, r3 = (p3 >> 16) << 2;
            float w;
            w = __shfl_sync(FULLM, rcw, r0+0); z0.x += w*v0.x; z0.y += w*v0.y;
            w = __shfl_sync(FULLM, rcw, r0+1); z1.x += w*v0.x; z1.y += w*v0.y;
            w = __shfl_sync(FULLM, rcw, r0+2); z2.x += w*v0.x; z2.y += w*v0.y;
            w = __shfl_sync(FULLM, rcw, r0+3); z3.x += w*v0.x; z3.y += w*v0.y;
            w = __shfl_sync(FULLM, rcw, r1+0); z0.x += w*v1.x; z0.y += w*v1.y;
            w = __shfl_sync(FULLM, rcw, r1+1); z1.x += w*v1.x; z1.y += w*v1.y;
            w = __shfl_sync(FULLM, rcw, r1+2); z2.x += w*v1.x; z2.y += w*v1.y;
            w = __shfl_sync(FULLM, rcw, r1+3); z3.x += w*v1.x; z3.y += w*v1.y;
            w = __shfl_sync(FULLM, rcw, r2+0); z0.x += w*v2.x; z0.y += w*v2.y;
            w = __shfl_sync(FULLM, rcw, r2+1); z1.x += w*v2.x; z1.y += w*v2.y;
            w = __shfl_sync(FULLM, rcw, r2+2); z2.x += w*v2.x; z2.y += w*v2.y;
            w = __shfl_sync(FULLM, rcw, r2+3); z3.x += w*v2.x; z3.y += w*v2.y;
            w = __shfl_sync(FULLM, rcw, r3+0); z0.x += w*v3.x; z0.y += w*v3.y;
            w = __shfl_sync(FULLM, rcw, r3+1); z1.x += w*v3.x; z1.y += w*v3.y;
            w = __shfl_sync(FULLM, rcw, r3+2); z2.x += w*v3.x; z2.y += w*v3.y;
            w = __shfl_sync(FULLM, rcw, r3+3); z3.x += w*v3.x; z3.y += w*v3.y;
        }
        for (; j < cnt; j++) {
            int p0 = __shfl_sync(FULLM, pk, j);
            float2 v0 = Xb[(size_t)(p0 & 0xFFFF)*32 + lane];
            int r0 = (p0 >> 16) << 2;
            float w;
            w = __shfl_sync(FULLM, rcw, r0+0); z0.x += w*v0.x; z0.y += w*v0.y;
            w = __shfl_sync(FULLM, rcw, r0+1); z1.x += w*v0.x; z1.y += w*v0.y;
            w = __shfl_sync(FULLM, rcw, r0+2); z2.x += w*v0.x; z2.y += w*v0.y;
            w = __shfl_sync(FULLM, rcw, r0+3); z3.x += w*v0.x; z3.y += w*v0.y;
        }
    }
    float2* Zb = (float2*)g_Z;
    size_t o = (size_t)n*128;
    Zb[o + lane]      = z0;
    Zb[o + 32 + lane] = z1;
    Zb[o + 64 + lane] = z2;
    Zb[o + 96 + lane] = z3;
}

// ---------------- GAT per-node body (R5-proven: single-pass, no max shift) -----
__device__ __forceinline__ void gat_node(int n, int lane, const float* __restrict__ h,
                                         const float* __restrict__ bias,
                                         float* __restrict__ Y, int C, int relu) {
    int s = g_rowptr[n*RR];
    int t = g_rowptr[n*RR + RR];
    float2 dn  = ((const float2*)g_dn)[n];
    float2 snn = ((const float2*)g_sn)[n];
    bool act = (2*lane < C);
    int C2 = C >> 1;
    const float2* hb = (const float2*)h;   // row stride = C float2
    float den0l = 0.f, den1l = 0.f;
    float2 acc0, acc1;
    {   // self-loop
        float e0 = __expf(leaky(snn.x + dn.x));
        float e1 = __expf(leaky(snn.y + dn.y));
        if (lane == 0) { den0l = e0; den1l = e1; }
        size_t ro = (size_t)n*C;
        float2 v0 = act ? hb[ro + lane]      : make_float2(0.f,0.f);
        float2 v1 = act ? hb[ro + C2 + lane] : make_float2(0.f,0.f);
        acc0 = make_float2(e0*v0.x, e0*v0.y);
        acc1 = make_float2(e1*v1.x, e1*v1.y);
    }
    for (int base = s; base < t; base += 32) {
        int cnt = min(32, t - base);
        int pk = 0; float e0l = 0.f, e1l = 0.f;
        if (lane < cnt) {
            pk = g_epack[base + lane];
            float2 sv = ((const float2*)g_sn)[pk & 0xFFFF];
            e0l = __expf(leaky(sv.x + dn.x));
            e1l = __expf(leaky(sv.y + dn.y));
        }
        den0l += e0l; den1l += e1l;
        int j = 0;
        for (; j + 4 <= cnt; j += 4) {
            int p0 = __shfl_sync(FULLM, pk, j);
            int p1 = __shfl_sync(FULLM, pk, j+1);
            int p2 = __shfl_sync(FULLM, pk, j+2);
            int p3 = __shfl_sync(FULLM, pk, j+3);
            float f00 = __shfl_sync(FULLM, e0l, j),   f10 = __shfl_sync(FULLM, e1l, j);
            float f01 = __shfl_sync(FULLM, e0l, j+1), f11 = __shfl_sync(FULLM, e1l, j+1);
            float f02 = __shfl_sync(FULLM, e0l, j+2), f12 = __shfl_sync(FULLM, e1l, j+2);
            float f03 = __shfl_sync(FULLM, e0l, j+3), f13 = __shfl_sync(FULLM, e1l, j+3);
            size_t r0 = (size_t)(p0 & 0xFFFF)*C, r1 = (size_t)(p1 & 0xFFFF)*C;
            size_t r2 = (size_t)(p2 & 0xFFFF)*C, r3 = (size_t)(p3 & 0xFFFF)*C;
            float2 zr = make_float2(0.f,0.f);
            float2 a0 = act ? hb[r0 + lane] : zr, b0 = act ? hb[r0 + C2 + lane] : zr;
            float2 a1 = act ? hb[r1 + lane] : zr, b1 = act ? hb[r1 + C2 + lane] : zr;
            float2 a2 = act ? hb[r2 + lane] : zr, b2 = act ? hb[r2 + C2 + lane] : zr;
            float2 a3 = act ? hb[r3 + lane] : zr, b3 = act ? hb[r3 + C2 + lane] : zr;
            acc0.x += f00*a0.x; acc0.y += f00*a0.y; acc1.x += f10*b0.x; acc1.y += f10*b0.y;
            acc0.x += f01*a1.x; acc0.y += f01*a1.y; acc1.x += f11*b1.x; acc1.y += f11*b1.y;
            acc0.x += f02*a2.x; acc0.y += f02*a2.y; acc1.x += f12*b2.x; acc1.y += f12*b2.y;
            acc0.x += f03*a3.x; acc0.y += f03*a3.y; acc1.x += f13*b3.x; acc1.y += f13*b3.y;
        }
        for (; j < cnt; j++) {
            int p0 = __shfl_sync(FULLM, pk, j);
            float f0 = __shfl_sync(FULLM, e0l, j), f1 = __shfl_sync(FULLM, e1l, j);
            size_t r0 = (size_t)(p0 & 0xFFFF)*C;
            float2 zr = make_float2(0.f,0.f);
            float2 a0 = act ? hb[r0 + lane] : zr, b0 = act ? hb[r0 + C2 + lane] : zr;
            acc0.x += f0*a0.x; acc0.y += f0*a0.y;
            acc1.x += f1*b0.x; acc1.y += f1*b0.y;
        }
    }
#pragma unroll
    for (int off = 16; off; off >>= 1) {
        den0l += __shfl_xor_sync(FULLM, den0l, off);
        den1l += __shfl_xor_sync(FULLM, den1l, off);
    }
    if (act) {
        float i0 = 1.f/den0l, i1 = 1.f/den1l;
        int c = 2*lane;
        float vx = 0.5f*(acc0.x*i0 + acc1.x*i1) + bias[c];
        float vy = 0.5f*(acc0.y*i0 + acc1.y*i1) + bias[c + 1];
        if (relu) { vx = fmaxf(vx, 0.f); vy = fmaxf(vy, 0.f); }
        Y[(size_t)n*C + c]     = vx;
        Y[(size_t)n*C + c + 1] = vy;
    }
}

// ---------------- fused per-layer aggregation: GAT warps first, then RGCN -----
__global__ void k_agg(const float* __restrict__ XR, const float* __restrict__ rc,
                      const float* __restrict__ h, const float* __restrict__ gb,
                      float* __restrict__ Yg, int C, int relu) {
    int gw = (blockIdx.x*blockDim.x + threadIdx.x) >> 5;
    int lane = threadIdx.x & 31;
    if (gw < NN)          gat_node(gw, lane, h, gb, Yg, C, relu);
    else if (gw < 2*NN)   rgcn_node(gw - NN, lane, XR, rc);
}

// ---------------- TF32 tensor-core GEMM ----------------
__device__ __forceinline__ unsigned f2tf(float x) {
    unsigned r;
    asm("cvt.rna.tf32.f32 %0, %1;" : "=r"(r) : "f"(x));
    return r;
}
__device__ __forceinline__ void mma_tf32(float d[4], const unsigned a[4],
                                         const unsigned b[2], const float c[4]) {
    asm volatile(
        "mma.sync.aligned.m16n8k8.row.col.f32.tf32.tf32.f32 "
        "{%0,%1,%2,%3}, {%4,%5,%6,%7}, {%8,%9}, {%10,%11,%12,%13};\n"
        : "=f"(d[0]), "=f"(d[1]), "=f"(d[2]), "=f"(d[3])
        : "r"(a[0]), "r"(a[1]), "r"(a[2]), "r"(a[3]),
          "r"(b[0]), "r"(b[1]),
          "f"(c[0]), "f"(c[1]), "f"(c[2]), "f"(c[3]));
}

#define BM 128
#define BN 64
#define BK 32
#define KSTR (BK + 4)

__device__ __forceinline__ void ld_tileA(const float* __restrict__ A, int K, int M,
                                         int m0, int k0, int tid, float4 pa[4]) {
#pragma unroll
    for (int it = 0; it < 4; it++) {
        int idx = tid + it*256;
        int m = idx >> 3, kq = (idx & 7) << 2;
        int gm = m0 + m;
        pa[it] = (gm < M) ? *reinterpret_cast<const float4*>(&A[(size_t)gm*K + k0 + kq])
                          : make_float4(0.f,0.f,0.f,0.f);
    }
}
__device__ __forceinline__ void ld_tileB(const float* __restrict__ Bm, int NC,
                                         int n0, int k0, int tid, float pb[8]) {
#pragma unroll
    for (int it = 0; it < 8; it++) {
        int idx = tid + it*256;
        int k = idx >> 6, nn = idx & 63;
        int gn = n0 + nn;
        pb[it] = (gn < NC) ? Bm[(size_t)(k0 + k)*NC + gn] : 0.f;
    }
}

// mainloop only; caller owns shared memory and epilogue
__device__ __forceinline__ void gemm_core(
    unsigned (*As)[KSTR], unsigned (*Bs)[KSTR],
    const float* __restrict__ A1, const float* __restrict__ B1, int K1,
    const float* __restrict__ A2, const float* __restrict__ B2, int K2,
    int M, int NC, int m0, int n0, int tid,
    int warp_m, int warp_n, int g, int t,
    float acc[2][4][4])
{
    float4 pa[4];
    float  pb[8];
    for (int pass = 0; pass < 2; pass++) {
        const float* A  = pass ? A2 : A1;
        const float* Bm = pass ? B2 : B1;
        int K = pass ? K2 : K1;
        if (K == 0 || A == nullptr) continue;
        ld_tileA(A, K, M, m0, 0, tid, pa);
        ld_tileB(Bm, NC, n0, 0, tid, pb);
        for (int k0 = 0; k0 < K; k0 += BK) {
#pragma unroll
            for (int it = 0; it < 4; it++) {
                int idx = tid + it*256;
                int m = idx >> 3, kq = (idx & 7) << 2;
                unsigned* p = &As[m][kq];
                p[0] = f2tf(pa[it].x); p[1] = f2tf(pa[it].y);
                p[2] = f2tf(pa[it].z); p[3] = f2tf(pa[it].w);
            }
#pragma unroll
            for (int it = 0; it < 8; it++) {
                int idx = tid + it*256;
                int k = idx >> 6, nn = idx & 63;
                Bs[nn][k] = f2tf(pb[it]);
            }
            __syncthreads();
            if (k0 + BK < K) {
                ld_tileA(A, K, M, m0, k0 + BK, tid, pa);
                ld_tileB(Bm, NC, n0, k0 + BK, tid, pb);
            }
#pragma unroll
            for (int kk = 0; kk < BK; kk += 8) {
                unsigned afr[2][4];
#pragma unroll
                for (int am = 0; am < 2; am++) {
                    int row = warp_m + am*16 + g;
                    afr[am][0] = As[row][kk + t];
                    afr[am][1] = As[row + 8][kk + t];
                    afr[am][2] = As[row][kk + t + 4];
                    afr[am][3] = As[row + 8][kk + t + 4];
                }
                unsigned bfr[4][2];
#pragma unroll
                for (int an = 0; an < 4; an++) {
                    int col = warp_n + an*8 + g;
                    bfr[an][0] = Bs[col][kk + t];
                    bfr[an][1] = Bs[col][kk + t + 4];
                }
#pragma unroll
                for (int am = 0; am < 2; am++)
#pragma unroll
                    for (int an = 0; an < 4; an++)
                        mma_tf32(acc[am][an], afr[am], bfr[an], acc[am][an]);
            }
            __syncthreads();
        }
    }
}

// generic body; if attC != 0, fuse attention dots (block fully inside one head:
// head = n0/attC). Race-free: register partials -> shfl over t -> 1 atomic/row.
__device__ __forceinline__ void gemm_body(
    const float* __restrict__ A1, const float* __restrict__ B1, int K1,
    const float* __restrict__ A2, const float* __restrict__ B2, int K2,
    const float* __restrict__ bias, float* __restrict__ Y,
    int M, int NC, int relu, int bx, int by,
    const float* __restrict__ gas, const float* __restrict__ gad, int attC)
{
    __shared__ __align__(16) unsigned As[BM][KSTR];
    __shared__ __align__(16) unsigned Bs[BN][KSTR];
    __shared__ float sdot[BM][2];
    int tid = threadIdx.x;
    int wid = tid >> 5, lane = tid & 31;
    int g = lane >> 2, t = lane & 3;
    int warp_m = (wid >> 1) * 32;
    int warp_n = (wid & 1) * 32;
    int m0 = by * BM, n0 = bx * BN;
    if (attC) for (int i = tid; i < BM*2; i += 256) ((float*)sdot)[i] = 0.f;
    float acc[2][4][4] = {};
    gemm_core(As, Bs, A1, B1, K1, A2, B2, K2, M, NC, m0, n0, tid, warp_m, warp_n, g, t, acc);
    float psn[2][2] = {}, pdn[2][2] = {};
#pragma unroll
    for (int am = 0; am < 2; am++) {
#pragma unroll
        for (int an = 0; an < 4; an++) {
#pragma unroll
            for (int i = 0; i < 4; i++) {
                int row = warp_m + am*16 + g + (i >> 1)*8;
                int col = warp_n + an*8 + 2*t + (i & 1);
                int gm = m0 + row, gn = n0 + col;
                if (gm < M && gn < NC) {
                    float v = acc[am][an][i] + (bias ? bias[gn] : 0.f);
                    if (relu) v = fmaxf(v, 0.f);
                    Y[(size_t)gm*NC + gn] = v;
                    if (attC) {
                        psn[am][i >> 1] += v * gas[gn];
                        pdn[am][i >> 1] += v * gad[gn];
                    }
                }
            }
        }
    }
    if (attC) {
#pragma unroll
        for (int am = 0; am < 2; am++)
#pragma unroll
            for (int ih = 0; ih < 2; ih++) {
                float ps = psn[am][ih], pd = pdn[am][ih];
                ps += __shfl_xor_sync(FULLM, ps, 1); ps += __shfl_xor_sync(FULLM, ps, 2);
                pd += __shfl_xor_sync(FULLM, pd, 1); pd += __shfl_xor_sync(FULLM, pd, 2);
                if (t == 0) {
                    int row = warp_m + am*16 + g + ih*8;
                    atomicAdd(&sdot[row][0], ps);
                    atomicAdd(&sdot[row][1], pd);
                }
            }
        __syncthreads();
        if (tid < BM) {
            int gm = m0 + tid;
            if (gm < M) {
                int head = n0 / attC;
                g_sn[gm*2 + head] = sdot[tid][0];
                g_dn[gm*2 + head] = sdot[tid][1];
            }
        }
    }
}

// two independent GEMMs in one launch; blockIdx.z selects the problem.
// q-part carries fused attdot (qattC).
__global__ void k_gemm_dual(
    const float* __restrict__ pA1, const float* __restrict__ pB1, int pK1,
    const float* __restrict__ pA2, const float* __restrict__ pB2, int pK2,
    const float* __restrict__ pbias, float* __restrict__ pY,
    int pM, int pNC, int prelu, int pGX,
    const float* __restrict__ qA1, const float* __restrict__ qB1, int qK1,
    const float* __restrict__ qbias, float* __restrict__ qY,
    int qM, int qNC, int qrelu, int qGX,
    const float* __restrict__ qgas, const float* __restrict__ qgad, int qattC)
{
    if (blockIdx.z == 0) {
        if ((int)blockIdx.x >= pGX) return;
        gemm_body(pA1, pB1, pK1, pA2, pB2, pK2, pbias, pY, pM, pNC, prelu,
                  blockIdx.x, blockIdx.y, nullptr, nullptr, 0);
    } else {
        if ((int)blockIdx.x >= qGX) return;
        gemm_body(qA1, qB1, qK1, nullptr, nullptr, 0, qbias, qY, qM, qNC, qrelu,
                  blockIdx.x, blockIdx.y, qgas, qgad, qattC);
    }
}

// ---- chained: C = relu(Z@rb1 + A@rr1 + bias) in smem; h = C @ gw2 + attdot2 --
__global__ void __launch_bounds__(256) k_gemm_chain(
    const float* __restrict__ Z, const float* __restrict__ rb1,
    const float* __restrict__ A, const float* __restrict__ rr1,
    const float* __restrict__ rbias1, const float* __restrict__ gw2,
    float* __restrict__ h,
    const float* __restrict__ gas2, const float* __restrict__ gad2)
{
    __shared__ __align__(16) char sbuf[128*68*4 + 32*68*4];   // 43520 B
    __shared__ float sdot[BM][4];   // sn0, dn0, sn1, dn1
    unsigned (*As)[KSTR] = reinterpret_cast<unsigned(*)[KSTR]>(sbuf);
    unsigned (*Bs)[KSTR] = reinterpret_cast<unsigned(*)[KSTR]>(sbuf + BM*KSTR*4);
    int tid = threadIdx.x;
    int wid = tid >> 5, lane = tid & 31;
    int g = lane >> 2, t = lane & 3;
    int warp_m = (wid >> 1) * 32;
    int warp_n = (wid & 1) * 32;
    int m0 = blockIdx.x * BM;

    float acc[2][4][4] = {};
    gemm_core(As, Bs, Z, rb1, BB*64, A, rr1, 64, NN, 64, m0, 0, tid, warp_m, warp_n, g, t, acc);
    // phase 2 smem views (overlap As/Bs; all reads drained by last sync in core)
    unsigned (*Cs)[68]  = reinterpret_cast<unsigned(*)[68]>(sbuf);
    unsigned (*Bs2)[68] = reinterpret_cast<unsigned(*)[68]>(sbuf + 128*68*4);
#pragma unroll
    for (int am = 0; am < 2; am++)
#pragma unroll
        for (int an = 0; an < 4; an++)
#pragma unroll
            for (int i = 0; i < 4; i++) {
                int row = warp_m + am*16 + g + (i >> 1)*8;
                int col = warp_n + an*8 + 2*t + (i & 1);
                float v = fmaxf(acc[am][an][i] + rbias1[col], 0.f);
                Cs[row][col] = f2tf(v);
            }
    for (int idx = tid; idx < 64*32; idx += 256) {
        int k = idx >> 5, nn = idx & 31;
        Bs2[nn][k] = f2tf(gw2[idx]);
    }
    __syncthreads();
    float acc2[2][4][4] = {};
#pragma unroll
    for (int kk = 0; kk < 64; kk += 8) {
        unsigned afr[2][4];
#pragma unroll
        for (int am = 0; am < 2; am++) {
            int row = warp_m + am*16 + g;
            afr[am][0] = Cs[row][kk + t];
            afr[am][1] = Cs[row + 8][kk + t];
            afr[am][2] = Cs[row][kk + t + 4];
            afr[am][3] = Cs[row + 8][kk + t + 4];
        }
        unsigned bfr[4][2];
#pragma unroll
        for (int an = 0; an < 4; an++) {
            int col = warp_n + an*8 + g;
            int cc = (col < 32) ? col : 0;
            bfr[an][0] = Bs2[cc][kk + t];
            bfr[an][1] = Bs2[cc][kk + t + 4];
        }
#pragma unroll
        for (int am = 0; am < 2; am++)
#pragma unroll
            for (int an = 0; an < 4; an++)
                mma_tf32(acc2[am][an], afr[am], bfr[an], acc2[am][an]);
    }
#pragma unroll
    for (int am = 0; am < 2; am++)
#pragma unroll
        for (int an = 0; an < 4; an++)
#pragma unroll
            for (int i = 0; i < 4; i++) {
                int row = warp_m + am*16 + g + (i >> 1)*8;
                int gn = warp_n + an*8 + 2*t + (i & 1);
                int gm = m0 + row;
                if (gm < NN && gn < 32)
                    h[(size_t)gm*32 + gn] = acc2[am][an][i];
            }
    // fused attdot2 (C=16): head0 = cols 0-15 (an 0,1), head1 = cols 16-31 (an 2,3).
    // Only warp_n==0 warps hold valid cols; each row touched by exactly one warp.
    if (warp_n == 0) {
#pragma unroll
        for (int am = 0; am < 2; am++)
#pragma unroll
            for (int ih = 0; ih < 2; ih++) {
                int row = warp_m + am*16 + g + ih*8;
                int gm = m0 + row;
                float s0 = 0.f, d0 = 0.f, s1 = 0.f, d1 = 0.f;
                if (gm < NN) {
#pragma unroll
                    for (int an = 0; an < 4; an++)
#pragma unroll
                        for (int par = 0; par < 2; par++) {
                            int gn = an*8 + 2*t + par;
                            float v = acc2[am][an][ih*2 + par];
                            float gsv = gas2[gn], gdv = gad2[gn];
                            if (an < 2) { s0 += v*gsv; d0 += v*gdv; }
                            else        { s1 += v*gsv; d1 += v*gdv; }
                        }
                }
                s0 += __shfl_xor_sync(FULLM, s0, 1); s0 += __shfl_xor_sync(FULLM, s0, 2);
                d0 += __shfl_xor_sync(FULLM, d0, 1); d0 += __shfl_xor_sync(FULLM, d0, 2);
                s1 += __shfl_xor_sync(FULLM, s1, 1); s1 += __shfl_xor_sync(FULLM, s1, 2);
                d1 += __shfl_xor_sync(FULLM, d1, 1); d1 += __shfl_xor_sync(FULLM, d1, 2);
                if (t == 0) {
                    sdot[row][0] = s0; sdot[row][1] = d0;
                    sdot[row][2] = s1; sdot[row][3] = d1;
                }
            }
    }
    __syncthreads();
    if (tid < BM) {
        int gm = m0 + tid;
        if (gm < NN) {
            g_sn[gm*2]     = sdot[tid][0];
            g_dn[gm*2]     = sdot[tid][1];
            g_sn[gm*2 + 1] = sdot[tid][2];
            g_dn[gm*2 + 1] = sdot[tid][3];
        }
    }
}

// ---- final rgcn GEMM (NC=16) fused with tanh(A + mean(Bf)) + g_deg re-zero ---
__global__ void __launch_bounds__(256) k_gemm_final(
    const float* __restrict__ Z, const float* __restrict__ rb2,
    const float* __restrict__ D, const float* __restrict__ rr2,
    const float* __restrict__ rbias2, const float* __restrict__ Bf,
    float* __restrict__ out)
{
    for (int i = blockIdx.x*blockDim.x + threadIdx.x; i < NR; i += gridDim.x*blockDim.x)
        g_deg[i] = 0;
    __shared__ __align__(16) unsigned As[BM][KSTR];
    __shared__ __align__(16) unsigned Bs[BN][KSTR];
    int tid = threadIdx.x;
    int wid = tid >> 5, lane = tid & 31;
    int g = lane >> 2, t = lane & 3;
    int warp_m = (wid >> 1) * 32;
    int warp_n = (wid & 1) * 32;
    int m0 = blockIdx.x * BM;

    float acc[2][4][4] = {};
    gemm_core(As, Bs, Z, rb2, BB*64, D, rr2, 64, NN, 16, m0, 0, tid, warp_m, warp_n, g, t, acc);
    float rmean[2][2];
#pragma unroll
    for (int am = 0; am < 2; am++)
#pragma unroll
        for (int ih = 0; ih < 2; ih++) {
            int gm = m0 + warp_m + am*16 + g + ih*8;
            float m = 0.f;
            if (t == 0 && gm < NN) {
                const float4* bp = (const float4*)(Bf + (size_t)gm*16);
                float4 b0 = bp[0], b1 = bp[1], b2 = bp[2], b3 = bp[3];
                m = ((b0.x+b0.y+b0.z+b0.w) + (b1.x+b1.y+b1.z+b1.w)
                   + (b2.x+b2.y+b2.z+b2.w) + (b3.x+b3.y+b3.z+b3.w)) * (1.f/16.f);
            }
            m = __shfl_sync(FULLM, m, lane & ~3);
            rmean[am][ih] = m;
        }
#pragma unroll
    for (int am = 0; am < 2; am++)
#pragma unroll
        for (int an = 0; an < 4; an++)
#pragma unroll
            for (int i = 0; i < 4; i++) {
                int row = warp_m + am*16 + g + (i >> 1)*8;
                int gn = warp_n + an*8 + 2*t + (i & 1);
                int gm = m0 + row;
                if (gm < NN && gn < 16) {
                    float v = acc[am][an][i] + rbias2[gn];
                    out[(size_t)gm*16 + gn] = tanhf(v + rmean[am][i >> 1]);
                }
            }
}

// ---- fused: gemm0 (x@gw0 -> h, NC=128, + attdot0) blocks, then scan_add ------
__global__ void k_sa_gemm0(const float* __restrict__ x, const float* __restrict__ gw0,
                           float* __restrict__ h, int gemmBlocks,
                           const float* __restrict__ gas0, const float* __restrict__ gad0) {
    int bid = blockIdx.x;
    if (bid < gemmBlocks) {
        gemm_body(x, gw0, 64, nullptr, nullptr, 0, nullptr, h, NN, 128, 0,
                  bid & 1, bid >> 1, gas0, gad0, 64);
    } else {
        int i = (bid - gemmBlocks)*blockDim.x + threadIdx.x;
        if (i < NR) {
            int v = g_rowptr[i+1] + g_boff[i >> 10];
            g_rowptr[i+1] = v;
            if (i + 1 < NR) g_cur[i+1] = v;
        }
        if (i == 0) { g_rowptr[0] = 0; g_cur[0] = 0; }
    }
}

// ---------------- host ----------------
extern "C" void kernel_launch(void* const* d_in, const int* in_sizes, int n_in,
                              void* d_out, int out_size) {
    const float* x  = (const float*)d_in[0];
    const int*   ei = (const int*)d_in[1];
    const int*   et = (const int*)d_in[2];
    const float *rb[3], *rc[3], *rrw[3], *rbias[3], *gw[3], *gas[3], *gad[3], *gb[3];
    for (int k = 0; k < 3; k++) {
        int base = 3 + k*8;
        rb[k]    = (const float*)d_in[base + 0];
        rc[k]    = (const float*)d_in[base + 1];
        rrw[k]   = (const float*)d_in[base + 2];
        rbias[k] = (const float*)d_in[base + 3];
        gw[k]    = (const float*)d_in[base + 4];
        gas[k]   = (const float*)d_in[base + 5];
        gad[k]   = (const float*)d_in[base + 6];
        gb[k]    = (const float*)d_in[base + 7];
    }
    float* out = (float*)d_out;

    float *Z, *h, *A, *Bf, *D;
    cudaGetSymbolAddress((void**)&Z, g_Z);
    cudaGetSymbolAddress((void**)&h, g_h);
    cudaGetSymbolAddress((void**)&A, g_bufA);
    cudaGetSymbolAddress((void**)&Bf, g_bufB);
    cudaGetSymbolAddress((void**)&D, g_bufD);

    dim3 blk(256);
    int aggGrid  = ((2*NN)*32 + 255)/256;
    int gy       = (NN + BM - 1)/BM;        // 391
    int gemm0B   = 2*gy;                    // 782 (NC=128, gx=2)
    int saB      = (NR + 255)/256;          // 1563
    int fillB    = (EE + 255)/256;          // 3125

    // ---- CSR build + GAT-0 projection+attdot (g_deg pre-zeroed by prior k_gemm_final) ----
    k_hist<<<fillB, 256>>>(ei, et);
    k_scan_block<<<(NR + 1023)/1024, 1024>>>();
    k_sa_gemm0<<<gemm0B + saB, blk>>>(x, gw[0], h, gemm0B, gas[0], gad[0]);
    k_fill<<<fillB, 256>>>(ei, et);

    // ---- layer 0: fused agg (gat h -> Bf, rgcn x -> Z) ----
    k_agg<<<aggGrid, 256>>>(x, rc[0], h, gb[0], Bf, 64, 1);
    // dual: rgcn0 GEMM (Z,rb0 + x,rr0 -> A)  ||  gat1 projection+attdot1 (Bf,gw1 -> h)
    {
        dim3 dgrid(2, gy, 2);
        k_gemm_dual<<<dgrid, blk>>>(
            Z, rb[0], BB*64, x, rrw[0], 64, rbias[0], A, NN, 64, 1, 1,
            Bf, gw[1], 64, nullptr, h, NN, 128, 0, 2,
            gas[1], gad[1], 64);
    }

    // ---- layer 1 agg, then chained rgcn1 GEMM + gat2 projection + attdot2 ----
    k_agg<<<aggGrid, 256>>>(A, rc[1], h, gb[1], D, 64, 1);
    k_gemm_chain<<<gy, blk>>>(Z, rb[1], A, rrw[1], rbias[1], gw[2], h, gas[2], gad[2]);

    // ---- layer 2 agg (gat D-branch -> Bf, rgcn D -> Z), then fused rgcn2+final ----
    k_agg<<<aggGrid, 256>>>(D, rc[2], h, gb[2], Bf, 16, 0);
    k_gemm_final<<<gy, blk>>>(Z, rb[2], D, rrw[2], rbias[2], Bf, out);
}